// round 6
// baseline (speedup 1.0000x reference)
#include <cuda_runtime.h>
#include <cuda_bf16.h>
#include <math.h>

// ---------------- problem constants ----------------
#define BATCH 16
#define IMG   512
#define PATCH 16
#define CIN   3
#define DIM   384
#define NHEAD 4
#define HDIM  96
#define NBLK  3
#define NCLS  2
#define NPAT  1024            // (512/16)^2
#define TOK   1025            // NPAT + 1
#define FFD   1536
#define BT    (BATCH*TOK)     // 16400
#define KPATCH (CIN*PATCH*PATCH) // 768

// ---------------- scratch (device globals, no allocs allowed) ----------------
__device__ float g_patches[BATCH*NPAT*KPATCH];   // 12.58M
__device__ float g_pe     [BATCH*NPAT*DIM];      // 6.29M
__device__ float g_h      [BT*DIM];
__device__ float g_hn     [BT*DIM];
__device__ float g_q      [BT*DIM];
__device__ float g_k      [BT*DIM];
__device__ float g_v      [BT*DIM];
__device__ float g_att    [BT*DIM];
__device__ float g_ff     [BT*FFD];              // 25.19M

// ---------------- im2col: x(16,3,512,512) -> patches (16384 x 768) ----------------
__global__ void im2col_kernel(const float* __restrict__ x, float* __restrict__ P)
{
    long idx = (long)blockIdx.x * blockDim.x + threadIdx.x;
    if (idx >= (long)BATCH*NPAT*KPATCH) return;
    int col = (int)(idx % KPATCH);
    long pi  = idx / KPATCH;
    int b  = (int)(pi / NPAT);
    int hw = (int)(pi % NPAT);
    int hh = hw >> 5, ww = hw & 31;
    int c = col >> 8;          // /256
    int r = col & 255;
    int p = r >> 4, q = r & 15;
    long xi = (((long)b*CIN + c)*IMG + (hh*PATCH + p))*IMG + (ww*PATCH + q);
    P[idx] = x[xi];
}

// ---------------- assemble h = [cls; pe+conv_b] + pos_emb ----------------
__global__ void assemble_kernel(const float* __restrict__ pe,
                                const float* __restrict__ conv_b,
                                const float* __restrict__ cls_tok,
                                const float* __restrict__ pos_emb,
                                float* __restrict__ h)
{
    long idx = (long)blockIdx.x * blockDim.x + threadIdx.x;
    if (idx >= (long)BT*DIM) return;
    int d  = (int)(idx % DIM);
    long bt = idx / DIM;
    int b   = (int)(bt / TOK);
    int tok = (int)(bt % TOK);
    float v = pos_emb[tok*DIM + d];
    if (tok == 0) v += cls_tok[d];
    else          v += pe[((long)b*NPAT + (tok-1))*DIM + d] + conv_b[d];
    h[idx] = v;
}

// ---------------- LayerNorm over last dim (384), one block / token ----------------
__global__ void ln_kernel(const float* __restrict__ X,
                          const float* __restrict__ gam,
                          const float* __restrict__ bet,
                          float* __restrict__ Y)
{
    int row = blockIdx.x;
    const float* xr = X + (size_t)row*DIM;
    int t = threadIdx.x;                       // 128 threads, 3 elems each
    float x0 = xr[t], x1 = xr[t+128], x2 = xr[t+256];
    float s = x0 + x1 + x2;
    __shared__ float red[4];
    __shared__ float red2[4];
    #pragma unroll
    for (int o = 16; o; o >>= 1) s += __shfl_down_sync(0xffffffffu, s, o);
    int w = t >> 5, l = t & 31;
    if (l == 0) red[w] = s;
    __syncthreads();
    if (t == 0) red[0] = (red[0]+red[1]+red[2]+red[3]) * (1.0f/DIM);
    __syncthreads();
    float mean = red[0];
    float d0 = x0-mean, d1 = x1-mean, d2 = x2-mean;
    float q = d0*d0 + d1*d1 + d2*d2;
    #pragma unroll
    for (int o = 16; o; o >>= 1) q += __shfl_down_sync(0xffffffffu, q, o);
    if (l == 0) red2[w] = q;
    __syncthreads();
    if (t == 0) red2[0] = rsqrtf((red2[0]+red2[1]+red2[2]+red2[3]) * (1.0f/DIM) + 1e-5f);
    __syncthreads();
    float rstd = red2[0];
    float* yr = Y + (size_t)row*DIM;
    yr[t]     = d0*rstd*gam[t]     + bet[t];
    yr[t+128] = d1*rstd*gam[t+128] + bet[t+128];
    yr[t+256] = d2*rstd*gam[t+256] + bet[t+256];
}

// ---------------- tiled SGEMM: C = op(A@B) [+bias][relu][+res] ----------------
// A: MxK row-major.  B: KxN row-major (TRANSB=false) or NxK row-major (TRANSB=true).
// Requirements: N % 128 == 0, K % 16 == 0 (holds for all uses). Only M is guarded.
template<bool TRANSB, bool BIAS, bool RELU, bool RES>
__global__ __launch_bounds__(256, 2)
void gemm128(int M, int N, int K,
             const float* __restrict__ A, const float* __restrict__ B,
             const float* __restrict__ bias, const float* __restrict__ Res,
             float* __restrict__ C)
{
    const int BK = 16;
    __shared__ float As[BK][128];
    __shared__ float Bs[BK][128];
    int tid = threadIdx.x;
    int bm = blockIdx.y * 128;
    int bn = blockIdx.x * 128;
    int tx = tid & 15, ty = tid >> 4;
    float acc[8][8];
    #pragma unroll
    for (int i = 0; i < 8; i++)
        #pragma unroll
        for (int j = 0; j < 8; j++) acc[i][j] = 0.f;

    for (int k0 = 0; k0 < K; k0 += BK) {
        // A tile: 128 rows x 16 cols, 512 float4s, 2 per thread, store transposed
        #pragma unroll
        for (int i = 0; i < 2; i++) {
            int lin = tid + i*256;
            int ar = lin >> 2, ac4 = (lin & 3) << 2;
            float4 a;
            if (bm + ar < M) a = *reinterpret_cast<const float4*>(A + (size_t)(bm+ar)*K + k0 + ac4);
            else             a = make_float4(0.f,0.f,0.f,0.f);
            As[ac4+0][ar] = a.x; As[ac4+1][ar] = a.y;
            As[ac4+2][ar] = a.z; As[ac4+3][ar] = a.w;
        }
        if (!TRANSB) {
            #pragma unroll
            for (int i = 0; i < 2; i++) {
                int lin = tid + i*256;
                int br = lin >> 5, bc4 = (lin & 31) << 2;
                float4 v = *reinterpret_cast<const float4*>(B + (size_t)(k0+br)*N + bn + bc4);
                *reinterpret_cast<float4*>(&Bs[br][bc4]) = v;
            }
        } else {
            #pragma unroll
            for (int i = 0; i < 2; i++) {
                int lin = tid + i*256;
                int nn = lin >> 2, kc4 = (lin & 3) << 2;
                float4 v = *reinterpret_cast<const float4*>(B + (size_t)(bn+nn)*K + k0 + kc4);
                Bs[kc4+0][nn] = v.x; Bs[kc4+1][nn] = v.y;
                Bs[kc4+2][nn] = v.z; Bs[kc4+3][nn] = v.w;
            }
        }
        __syncthreads();
        #pragma unroll
        for (int kk = 0; kk < BK; kk++) {
            float af[8], bf[8];
            *reinterpret_cast<float4*>(af)   = *reinterpret_cast<const float4*>(&As[kk][ty*8]);
            *reinterpret_cast<float4*>(af+4) = *reinterpret_cast<const float4*>(&As[kk][ty*8+4]);
            *reinterpret_cast<float4*>(bf)   = *reinterpret_cast<const float4*>(&Bs[kk][tx*8]);
            *reinterpret_cast<float4*>(bf+4) = *reinterpret_cast<const float4*>(&Bs[kk][tx*8+4]);
            #pragma unroll
            for (int i = 0; i < 8; i++)
                #pragma unroll
                for (int j = 0; j < 8; j++)
                    acc[i][j] = fmaf(af[i], bf[j], acc[i][j]);
        }
        __syncthreads();
    }
    #pragma unroll
    for (int i = 0; i < 8; i++) {
        int m = bm + ty*8 + i;
        if (m < M) {
            #pragma unroll
            for (int j = 0; j < 8; j++) {
                int n = bn + tx*8 + j;
                size_t idx = (size_t)m*N + n;
                float v = acc[i][j];
                if (BIAS) v += bias[n];
                if (RELU) v = fmaxf(v, 0.f);
                if (RES)  v += Res[idx];
                C[idx] = v;
            }
        }
    }
}

// ---------------- fused distance-attention (flash-style online softmax) ----------------
// Q/K/V layout: (B, T, NH*HD) row-major; block = (q_tile 32, head, batch), 128 threads.
#define AT_QT 32
#define AT_KT 64
#define ATTN_SMEM_FLOATS (2*AT_KT*97 + AT_QT*96 + AT_QT*65 + 4*AT_QT)
__global__ __launch_bounds__(128)
void attn_kernel(const float* __restrict__ Q, const float* __restrict__ Kp,
                 const float* __restrict__ V, float* __restrict__ O)
{
    extern __shared__ float sm[];
    float* Ks   = sm;                       // [64][97]
    float* Vs   = Ks + AT_KT*97;            // [64][97]
    float* Qs   = Vs + AT_KT*97;            // [32][96]
    float* Ssm  = Qs + AT_QT*96;            // [32][65]
    float* qq   = Ssm + AT_QT*65;
    float* mrow = qq + AT_QT;
    float* lrow = mrow + AT_QT;
    float* frow = lrow + AT_QT;

    const int tid = threadIdx.x;
    const int b = blockIdx.z, h = blockIdx.y;
    const int tq0 = blockIdx.x * AT_QT;
    const int nq = min(AT_QT, TOK - tq0);
    const float scale = 0.1020620726f;      // 1/sqrt(96)
    const size_t base = ((size_t)b*TOK)*DIM + h*HDIM;

    for (int idx = tid; idx < AT_QT*96; idx += 128) {
        int r = idx / 96, d = idx - r*96;
        Qs[idx] = (r < nq) ? Q[base + (size_t)(tq0+r)*DIM + d] : 0.f;
    }
    __syncthreads();
    if (tid < AT_QT) {
        float s = 0.f;
        #pragma unroll 8
        for (int d = 0; d < 96; d++) { float qv = Qs[tid*96+d]; s += qv*qv; }
        qq[tid] = s; mrow[tid] = -1e30f; lrow[tid] = 0.f; frow[tid] = 1.f;
        for (int j = 0; j < 65; j++) Ssm[tid*65 + j] = 0.f;   // keep AV garbage-free
    }
    float acc[AT_QT];
    #pragma unroll
    for (int i = 0; i < AT_QT; i++) acc[i] = 0.f;
    __syncthreads();

    for (int kt0 = 0; kt0 < TOK; kt0 += AT_KT) {
        int kn = min(AT_KT, TOK - kt0);
        for (int idx = tid; idx < AT_KT*96; idx += 128) {
            int r = idx / 96, d = idx - r*96;
            if (r < kn) {
                size_t g = base + (size_t)(kt0+r)*DIM + d;
                Ks[r*97+d] = Kp[g];
                Vs[r*97+d] = V[g];
            } else {
                Ks[r*97+d] = 0.f; Vs[r*97+d] = 0.f;
            }
        }
        __syncthreads();
        // scores: 128 threads = 64 keys x 2 q-halves
        {
            int j = tid & 63;
            int half = tid >> 6;
            if (j < kn) {
                float kk = 0.f;
                #pragma unroll 8
                for (int d = 0; d < 96; d++) { float kv = Ks[j*97+d]; kk += kv*kv; }
                int q1 = min(half*16 + 16, nq);
                for (int qi = half*16; qi < q1; qi++) {
                    float dot = 0.f;
                    #pragma unroll 8
                    for (int d = 0; d < 96; d++) dot = fmaf(Qs[qi*96+d], Ks[j*97+d], dot);
                    float d2 = qq[qi] + kk - 2.f*dot;
                    Ssm[qi*65 + j] = sqrtf(fmaxf(d2, 0.f)) * scale;
                }
            }
        }
        __syncthreads();
        // online softmax, thread per q-row
        if (tid < nq) {
            float mold = mrow[tid];
            float mt = mold;
            for (int j = 0; j < kn; j++) mt = fmaxf(mt, Ssm[tid*65+j]);
            float f = __expf(mold - mt);
            float l = lrow[tid] * f;
            for (int j = 0; j < kn; j++) {
                float p = __expf(Ssm[tid*65+j] - mt);
                Ssm[tid*65+j] = p;
                l += p;
            }
            for (int j = kn; j < AT_KT; j++) Ssm[tid*65+j] = 0.f;
            mrow[tid] = mt; lrow[tid] = l; frow[tid] = f;
        } else if (tid < AT_QT) {
            for (int j = 0; j < AT_KT; j++) Ssm[tid*65+j] = 0.f;
            frow[tid] = 1.f;
        }
        __syncthreads();
        // AV: thread per output dim d
        if (tid < 96) {
            #pragma unroll
            for (int qi = 0; qi < AT_QT; qi++) acc[qi] *= frow[qi];
            for (int j = 0; j < kn; j++) {
                float vv = Vs[j*97 + tid];
                #pragma unroll
                for (int qi = 0; qi < AT_QT; qi++)
                    acc[qi] = fmaf(Ssm[qi*65 + j], vv, acc[qi]);
            }
        }
        __syncthreads();
    }
    if (tid < 96) {
        for (int qi = 0; qi < nq; qi++)
            O[base + (size_t)(tq0+qi)*DIM + tid] = acc[qi] / lrow[qi];
    }
}

// ---------------- classifier head: logits[b][c] from cls-token rows ----------------
__global__ void head_kernel(const float* __restrict__ hn,
                            const float* __restrict__ pw,
                            const float* __restrict__ pb,
                            float* __restrict__ out)
{
    int b = blockIdx.x;
    int c = threadIdx.x >> 5;          // warp 0 -> class 0, warp 1 -> class 1
    int lane = threadIdx.x & 31;
    const float* row = hn + (size_t)b*TOK*DIM;   // token 0 of batch b
    float s = 0.f;
    for (int d = lane; d < DIM; d += 32) s = fmaf(row[d], pw[d*NCLS + c], s);
    #pragma unroll
    for (int o = 16; o; o >>= 1) s += __shfl_down_sync(0xffffffffu, s, o);
    if (lane == 0) out[b*NCLS + c] = s + pb[c];
}

// ---------------- cross-entropy loss over 2 classes ----------------
__global__ void loss_kernel(const float* __restrict__ logits,
                            const int* __restrict__ tgt,
                            float* __restrict__ out)
{
    if (threadIdx.x == 0 && blockIdx.x == 0) {
        float acc = 0.f;
        for (int b = 0; b < BATCH; b++) {
            float l0 = logits[2*b], l1 = logits[2*b+1];
            float mx = fmaxf(l0, l1);
            float lse = mx + logf(expf(l0-mx) + expf(l1-mx));
            acc += lse - logits[2*b + tgt[b]];
        }
        out[BATCH*NCLS] = acc * (1.0f/BATCH);
    }
}

// ---------------- launch ----------------
extern "C" void kernel_launch(void* const* d_in, const int* in_sizes, int n_in,
                              void* d_out, int out_size)
{
    const float* x       = (const float*)d_in[0];
    const int*   targets = (const int*)  d_in[1];
    const float* conv_w  = (const float*)d_in[2];
    const float* conv_b  = (const float*)d_in[3];
    const float* cls_tok = (const float*)d_in[4];
    const float* pos_emb = (const float*)d_in[5];
    const float* ln1_s   = (const float*)d_in[6];
    const float* ln1_b   = (const float*)d_in[7];
    const float* ln2_s   = (const float*)d_in[8];
    const float* ln2_b   = (const float*)d_in[9];
    const float* wq      = (const float*)d_in[10];
    const float* wk      = (const float*)d_in[11];
    const float* wv      = (const float*)d_in[12];
    const float* wo      = (const float*)d_in[13];
    const float* bo      = (const float*)d_in[14];
    const float* w1      = (const float*)d_in[15];
    const float* b1      = (const float*)d_in[16];
    const float* w2      = (const float*)d_in[17];
    const float* b2      = (const float*)d_in[18];
    const float* lnf_s   = (const float*)d_in[19];
    const float* lnf_b   = (const float*)d_in[20];
    const float* proj_w  = (const float*)d_in[21];
    const float* proj_b  = (const float*)d_in[22];
    float* out = (float*)d_out;

    float *p_patches, *p_pe, *p_h, *p_hn, *p_q, *p_k, *p_v, *p_att, *p_ff;
    cudaGetSymbolAddress((void**)&p_patches, g_patches);
    cudaGetSymbolAddress((void**)&p_pe,      g_pe);
    cudaGetSymbolAddress((void**)&p_h,       g_h);
    cudaGetSymbolAddress((void**)&p_hn,      g_hn);
    cudaGetSymbolAddress((void**)&p_q,       g_q);
    cudaGetSymbolAddress((void**)&p_k,       g_k);
    cudaGetSymbolAddress((void**)&p_v,       g_v);
    cudaGetSymbolAddress((void**)&p_att,     g_att);
    cudaGetSymbolAddress((void**)&p_ff,      g_ff);

    const int attn_smem = ATTN_SMEM_FLOATS * (int)sizeof(float);  // ~70.8 KB
    cudaFuncSetAttribute(attn_kernel, cudaFuncAttributeMaxDynamicSharedMemorySize, attn_smem);

    // --- patch embedding ---
    {
        long n = (long)BATCH*NPAT*KPATCH;
        im2col_kernel<<<(unsigned)((n + 255) / 256), 256>>>(x, p_patches);
    }
    gemm128<true,false,false,false><<<dim3(DIM/128, (BATCH*NPAT)/128), 256>>>(
        BATCH*NPAT, DIM, KPATCH, p_patches, conv_w, nullptr, nullptr, p_pe);
    {
        long n = (long)BT*DIM;
        assemble_kernel<<<(unsigned)((n + 255) / 256), 256>>>(p_pe, conv_b, cls_tok, pos_emb, p_h);
    }

    const int MT = (BT + 127) / 128;   // 129 M-tiles
    for (int i = 0; i < NBLK; i++) {
        const float* wq_i = wq + (size_t)i*DIM*DIM;
        const float* wk_i = wk + (size_t)i*DIM*DIM;
        const float* wv_i = wv + (size_t)i*DIM*DIM;
        const float* wo_i = wo + (size_t)i*DIM*DIM;
        const float* w1_i = w1 + (size_t)i*DIM*FFD;
        const float* w2_i = w2 + (size_t)i*FFD*DIM;

        ln_kernel<<<BT, 128>>>(p_h, ln1_s + i*DIM, ln1_b + i*DIM, p_hn);

        gemm128<false,false,false,false><<<dim3(DIM/128, MT), 256>>>(BT, DIM, DIM, p_hn, wq_i, nullptr, nullptr, p_q);
        gemm128<false,false,false,false><<<dim3(DIM/128, MT), 256>>>(BT, DIM, DIM, p_hn, wk_i, nullptr, nullptr, p_k);
        gemm128<false,false,false,false><<<dim3(DIM/128, MT), 256>>>(BT, DIM, DIM, p_hn, wv_i, nullptr, nullptr, p_v);

        attn_kernel<<<dim3((TOK + AT_QT - 1)/AT_QT, NHEAD, BATCH), 128, attn_smem>>>(p_q, p_k, p_v, p_att);

        // h = h + att @ wo + bo
        gemm128<false,true,false,true><<<dim3(DIM/128, MT), 256>>>(BT, DIM, DIM, p_att, wo_i, bo + i*DIM, p_h, p_h);

        ln_kernel<<<BT, 128>>>(p_h, ln2_s + i*DIM, ln2_b + i*DIM, p_hn);

        // ff = relu(hn @ w1 + b1)
        gemm128<false,true,true,false><<<dim3(FFD/128, MT), 256>>>(BT, FFD, DIM, p_hn, w1_i, b1 + i*FFD, nullptr, p_ff);
        // h = h + ff @ w2 + b2
        gemm128<false,true,false,true><<<dim3(DIM/128, MT), 256>>>(BT, DIM, FFD, p_ff, w2_i, b2 + i*DIM, p_h, p_h);
    }

    ln_kernel<<<BT, 128>>>(p_h, lnf_s, lnf_b, p_hn);
    head_kernel<<<BATCH, 64>>>(p_hn, proj_w, proj_b, out);
    loss_kernel<<<1, 32>>>(out, targets, out);
}

// round 7
// speedup vs baseline: 1.7676x; 1.7676x over previous
#include <cuda_runtime.h>
#include <cuda_bf16.h>
#include <math.h>

// ---------------- problem constants ----------------
#define BATCH 16
#define IMG   512
#define PATCH 16
#define CIN   3
#define DIM   384
#define NHEAD 4
#define HDIM  96
#define NBLK  3
#define NCLS  2
#define NPAT  1024            // (512/16)^2
#define TOK   1025            // NPAT + 1
#define FFD   1536
#define BT    (BATCH*TOK)     // 16400
#define KPATCH (CIN*PATCH*PATCH) // 768

// ---------------- packed f32x2 helpers (Blackwell FFMA2 path) ----------------
__device__ __forceinline__ unsigned long long splat2(float x) {
    unsigned long long r;
    asm("mov.b64 %0, {%1, %1};" : "=l"(r) : "f"(x));
    return r;
}
__device__ __forceinline__ void ffma2(unsigned long long &d, unsigned long long a, unsigned long long b) {
    asm("fma.rn.f32x2 %0, %1, %2, %0;" : "+l"(d) : "l"(a), "l"(b));
}
__device__ __forceinline__ unsigned long long fmul2(unsigned long long a, unsigned long long b) {
    unsigned long long r;
    asm("mul.rn.f32x2 %0, %1, %2;" : "=l"(r) : "l"(a), "l"(b));
    return r;
}
__device__ __forceinline__ float2 unpack2(unsigned long long v) {
    float2 f;
    asm("mov.b64 {%0, %1}, %2;" : "=f"(f.x), "=f"(f.y) : "l"(v));
    return f;
}

// ---------------- scratch (device globals, no allocs allowed) ----------------
__device__ float g_patches[BATCH*NPAT*KPATCH];
__device__ float g_pe     [BATCH*NPAT*DIM];
__device__ float g_h      [BT*DIM];
__device__ float g_hn     [BT*DIM];
__device__ float g_q      [BT*DIM];
__device__ float g_k      [BT*DIM];
__device__ float g_v      [BT*DIM];
__device__ float g_att    [BT*DIM];
__device__ float g_ff     [BT*FFD];

// ---------------- im2col ----------------
__global__ void im2col_kernel(const float* __restrict__ x, float* __restrict__ P)
{
    long idx = (long)blockIdx.x * blockDim.x + threadIdx.x;
    if (idx >= (long)BATCH*NPAT*KPATCH) return;
    int col = (int)(idx % KPATCH);
    long pi  = idx / KPATCH;
    int b  = (int)(pi / NPAT);
    int hw = (int)(pi % NPAT);
    int hh = hw >> 5, ww = hw & 31;
    int c = col >> 8;
    int r = col & 255;
    int p = r >> 4, q = r & 15;
    long xi = (((long)b*CIN + c)*IMG + (hh*PATCH + p))*IMG + (ww*PATCH + q);
    P[idx] = x[xi];
}

// ---------------- assemble h = [cls; pe+conv_b] + pos_emb ----------------
__global__ void assemble_kernel(const float* __restrict__ pe,
                                const float* __restrict__ conv_b,
                                const float* __restrict__ cls_tok,
                                const float* __restrict__ pos_emb,
                                float* __restrict__ h)
{
    long idx = (long)blockIdx.x * blockDim.x + threadIdx.x;
    if (idx >= (long)BT*DIM) return;
    int d  = (int)(idx % DIM);
    long bt = idx / DIM;
    int b   = (int)(bt / TOK);
    int tok = (int)(bt % TOK);
    float v = pos_emb[tok*DIM + d];
    if (tok == 0) v += cls_tok[d];
    else          v += pe[((long)b*NPAT + (tok-1))*DIM + d] + conv_b[d];
    h[idx] = v;
}

// ---------------- LayerNorm ----------------
__global__ void ln_kernel(const float* __restrict__ X,
                          const float* __restrict__ gam,
                          const float* __restrict__ bet,
                          float* __restrict__ Y)
{
    int row = blockIdx.x;
    const float* xr = X + (size_t)row*DIM;
    int t = threadIdx.x;
    float x0 = xr[t], x1 = xr[t+128], x2 = xr[t+256];
    float s = x0 + x1 + x2;
    __shared__ float red[4];
    __shared__ float red2[4];
    #pragma unroll
    for (int o = 16; o; o >>= 1) s += __shfl_down_sync(0xffffffffu, s, o);
    int w = t >> 5, l = t & 31;
    if (l == 0) red[w] = s;
    __syncthreads();
    if (t == 0) red[0] = (red[0]+red[1]+red[2]+red[3]) * (1.0f/DIM);
    __syncthreads();
    float mean = red[0];
    float d0 = x0-mean, d1 = x1-mean, d2 = x2-mean;
    float q = d0*d0 + d1*d1 + d2*d2;
    #pragma unroll
    for (int o = 16; o; o >>= 1) q += __shfl_down_sync(0xffffffffu, q, o);
    if (l == 0) red2[w] = q;
    __syncthreads();
    if (t == 0) red2[0] = rsqrtf((red2[0]+red2[1]+red2[2]+red2[3]) * (1.0f/DIM) + 1e-5f);
    __syncthreads();
    float rstd = red2[0];
    float* yr = Y + (size_t)row*DIM;
    yr[t]     = d0*rstd*gam[t]     + bet[t];
    yr[t+128] = d1*rstd*gam[t+128] + bet[t+128];
    yr[t+256] = d2*rstd*gam[t+256] + bet[t+256];
}

// ---------------- SGEMM core: f32x2 FMA, double-buffered smem ----------------
// C = op(A@B) [+bias][relu][+res].  A: MxK rm.  B: KxN rm (!TRANSB) / NxK rm (TRANSB).
// N%128==0, K%16==0 required (holds everywhere). M guarded.
template<bool TRANSB, bool BIAS, bool RELU, bool RES>
__device__ __forceinline__ void gemm_core(
    int M, int N, int K,
    const float* __restrict__ A, const float* __restrict__ B,
    const float* __restrict__ bias, const float* __restrict__ Res,
    float* __restrict__ C,
    float (&As)[2][16][128], float (&Bs)[2][16][128])
{
    const int tid = threadIdx.x;
    const int bm = blockIdx.y * 128;
    const int bn = blockIdx.x * 128;
    const int tx = tid & 15, ty = tid >> 4;
    const int ar = tid >> 2, ac4 = (tid & 3) << 2;   // A loader: rows ar, ar+64
    const int br = tid >> 5, bc4 = (tid & 31) << 2;  // B loader (!TRANSB)
    const int nn = tid >> 2, kc4 = (tid & 3) << 2;   // B loader (TRANSB)

    unsigned long long acc[8][4];
    #pragma unroll
    for (int i = 0; i < 8; i++)
        #pragma unroll
        for (int j = 0; j < 4; j++) acc[i][j] = 0ull;

    float4 ra0, ra1, rb0, rb1;
    const float4 f40 = make_float4(0.f,0.f,0.f,0.f);

    auto ldg = [&](int k0) {
        ra0 = (bm+ar    < M) ? *reinterpret_cast<const float4*>(A + (size_t)(bm+ar   )*K + k0 + ac4) : f40;
        ra1 = (bm+ar+64 < M) ? *reinterpret_cast<const float4*>(A + (size_t)(bm+ar+64)*K + k0 + ac4) : f40;
        if (!TRANSB) {
            rb0 = *reinterpret_cast<const float4*>(B + (size_t)(k0+br  )*N + bn + bc4);
            rb1 = *reinterpret_cast<const float4*>(B + (size_t)(k0+br+8)*N + bn + bc4);
        } else {
            rb0 = *reinterpret_cast<const float4*>(B + (size_t)(bn+nn   )*K + k0 + kc4);
            rb1 = *reinterpret_cast<const float4*>(B + (size_t)(bn+nn+64)*K + k0 + kc4);
        }
    };
    auto sts = [&](int bf) {
        As[bf][ac4+0][ar] = ra0.x; As[bf][ac4+1][ar] = ra0.y;
        As[bf][ac4+2][ar] = ra0.z; As[bf][ac4+3][ar] = ra0.w;
        As[bf][ac4+0][ar+64] = ra1.x; As[bf][ac4+1][ar+64] = ra1.y;
        As[bf][ac4+2][ar+64] = ra1.z; As[bf][ac4+3][ar+64] = ra1.w;
        if (!TRANSB) {
            *reinterpret_cast<float4*>(&Bs[bf][br  ][bc4]) = rb0;
            *reinterpret_cast<float4*>(&Bs[bf][br+8][bc4]) = rb1;
        } else {
            Bs[bf][kc4+0][nn] = rb0.x; Bs[bf][kc4+1][nn] = rb0.y;
            Bs[bf][kc4+2][nn] = rb0.z; Bs[bf][kc4+3][nn] = rb0.w;
            Bs[bf][kc4+0][nn+64] = rb1.x; Bs[bf][kc4+1][nn+64] = rb1.y;
            Bs[bf][kc4+2][nn+64] = rb1.z; Bs[bf][kc4+3][nn+64] = rb1.w;
        }
    };

    ldg(0); sts(0); __syncthreads();
    int buf = 0;
    for (int k0 = 0; k0 < K; k0 += 16) {
        bool more = (k0 + 16) < K;
        if (more) ldg(k0 + 16);
        #pragma unroll
        for (int kk = 0; kk < 16; kk++) {
            float4 a0 = *reinterpret_cast<const float4*>(&As[buf][kk][ty*8]);
            float4 a1 = *reinterpret_cast<const float4*>(&As[buf][kk][ty*8+4]);
            union { float4 v[2]; unsigned long long u[4]; } bu;
            bu.v[0] = *reinterpret_cast<const float4*>(&Bs[buf][kk][tx*8]);
            bu.v[1] = *reinterpret_cast<const float4*>(&Bs[buf][kk][tx*8+4]);
            float av[8] = {a0.x,a0.y,a0.z,a0.w,a1.x,a1.y,a1.z,a1.w};
            #pragma unroll
            for (int i = 0; i < 8; i++) {
                unsigned long long ap = splat2(av[i]);
                ffma2(acc[i][0], ap, bu.u[0]);
                ffma2(acc[i][1], ap, bu.u[1]);
                ffma2(acc[i][2], ap, bu.u[2]);
                ffma2(acc[i][3], ap, bu.u[3]);
            }
        }
        if (more) sts(buf ^ 1);
        __syncthreads();
        buf ^= 1;
    }

    #pragma unroll
    for (int i = 0; i < 8; i++) {
        int m = bm + ty*8 + i;
        if (m < M) {
            #pragma unroll
            for (int jp = 0; jp < 4; jp++) {
                float2 u = unpack2(acc[i][jp]);
                int n = bn + tx*8 + 2*jp;
                size_t idx = (size_t)m*N + n;
                if (BIAS) { u.x += bias[n]; u.y += bias[n+1]; }
                if (RELU) { u.x = fmaxf(u.x, 0.f); u.y = fmaxf(u.y, 0.f); }
                if (RES)  { float2 r = *reinterpret_cast<const float2*>(Res + idx);
                            u.x += r.x; u.y += r.y; }
                *reinterpret_cast<float2*>(C + idx) = u;
            }
        }
    }
}

template<bool TRANSB, bool BIAS, bool RELU, bool RES>
__global__ __launch_bounds__(256, 2)
void gemm128(int M, int N, int K,
             const float* __restrict__ A, const float* __restrict__ B,
             const float* __restrict__ bias, const float* __restrict__ Res,
             float* __restrict__ C)
{
    __shared__ float As[2][16][128];
    __shared__ float Bs[2][16][128];
    gemm_core<TRANSB,BIAS,RELU,RES>(M, N, K, A, B, bias, Res, C, As, Bs);
}

// Fused Q/K/V projection: blockIdx.z selects which weight/output.
__global__ __launch_bounds__(256, 2)
void gemm128_qkv(int M, int K, const float* __restrict__ A,
                 const float* __restrict__ B0, const float* __restrict__ B1,
                 const float* __restrict__ B2,
                 float* __restrict__ C0, float* __restrict__ C1, float* __restrict__ C2)
{
    __shared__ float As[2][16][128];
    __shared__ float Bs[2][16][128];
    const float* B = (blockIdx.z == 0) ? B0 : ((blockIdx.z == 1) ? B1 : B2);
    float*       C = (blockIdx.z == 0) ? C0 : ((blockIdx.z == 1) ? C1 : C2);
    gemm_core<false,false,false,false>(M, DIM, K, A, B, nullptr, nullptr, C, As, Bs);
}

// ---------------- fused distance-attention (flash-style, f32x2) ----------------
// Q/K/V layout: (B, T, NH*HD) row-major; block = (q_tile 32, head, batch), 128 thr.
#define AT_QT 32
#define AT_KT 64
#define KVS 98              // K/V smem row stride (even -> b64-aligned)
#define SST 34              // Ssm stride: Ssm[j][qi], even for b64 pairs along qi
#define ATTN_SMEM_FLOATS (2*AT_KT*KVS + AT_QT*96 + AT_KT*SST + 4*AT_QT)
__global__ __launch_bounds__(128)
void attn_kernel(const float* __restrict__ Q, const float* __restrict__ Kp,
                 const float* __restrict__ V, float* __restrict__ O)
{
    extern __shared__ float sm[];
    float* Ks   = sm;                       // [64][98]
    float* Vs   = Ks + AT_KT*KVS;           // [64][98]
    float* Qs   = Vs + AT_KT*KVS;           // [32][96]
    float* Ssm  = Qs + AT_QT*96;            // [64][34]  transposed: [j][qi]
    float* qq   = Ssm + AT_KT*SST;
    float* mrow = qq + AT_QT;
    float* lrow = mrow + AT_QT;
    float* frow = lrow + AT_QT;

    const int tid = threadIdx.x;
    const int b = blockIdx.z, h = blockIdx.y;
    const int tq0 = blockIdx.x * AT_QT;
    const int nq = min(AT_QT, TOK - tq0);
    const float scale = 0.1020620726f;      // 1/sqrt(96)
    const size_t base = ((size_t)b*TOK)*DIM + h*HDIM;

    // load Q (float4, zero-padded rows)
    for (int idx = tid; idx < AT_QT*24; idx += 128) {
        int r = idx / 24, c = idx - r*24;
        float4 v = (r < nq) ? *reinterpret_cast<const float4*>(Q + base + (size_t)(tq0+r)*DIM + 4*c)
                            : make_float4(0.f,0.f,0.f,0.f);
        *reinterpret_cast<float4*>(&Qs[r*96 + 4*c]) = v;
    }
    for (int idx = tid; idx < AT_KT*SST; idx += 128) Ssm[idx] = 0.f;
    __syncthreads();
    if (tid < AT_QT) {
        float s = 0.f;
        #pragma unroll 8
        for (int d = 0; d < 96; d++) { float qv = Qs[tid*96+d]; s += qv*qv; }
        qq[tid] = s; mrow[tid] = -1e30f; lrow[tid] = 0.f; frow[tid] = 1.f;
    }
    unsigned long long accp[16];            // 32 q-rows paired, per output dim
    #pragma unroll
    for (int p = 0; p < 16; p++) accp[p] = 0ull;
    __syncthreads();

    const int j    = tid & 63;
    const int half = tid >> 6;

    for (int kt0 = 0; kt0 < TOK; kt0 += AT_KT) {
        int kn = min(AT_KT, TOK - kt0);
        // load K,V (float2, zero-padded)
        for (int idx = tid; idx < AT_KT*48; idx += 128) {
            int r = idx / 48, c = idx - r*48;
            float2 kv2, vv2;
            if (r < kn) {
                size_t g = base + (size_t)(kt0+r)*DIM;
                kv2 = *reinterpret_cast<const float2*>(Kp + g + 2*c);
                vv2 = *reinterpret_cast<const float2*>(V  + g + 2*c);
            } else { kv2 = make_float2(0.f,0.f); vv2 = kv2; }
            *reinterpret_cast<float2*>(&Ks[r*KVS + 2*c]) = kv2;
            *reinterpret_cast<float2*>(&Vs[r*KVS + 2*c]) = vv2;
        }
        __syncthreads();

        // ---- scores: thread owns key j, computes 16 q-rows ----
        {
            const unsigned long long* krow = reinterpret_cast<const unsigned long long*>(&Ks[j*KVS]);
            // |k|^2 (two chains for ILP)
            unsigned long long ka = 0ull, kb = 0ull;
            #pragma unroll
            for (int p = 0; p < 48; p += 2) {
                unsigned long long k0 = krow[p], k1 = krow[p+1];
                ffma2(ka, k0, k0); ffma2(kb, k1, k1);
            }
            float2 ku = unpack2(ka), kv = unpack2(kb);
            float kk = ku.x + ku.y + kv.x + kv.y;

            unsigned long long dotp[16];
            #pragma unroll
            for (int q = 0; q < 16; q++) dotp[q] = 0ull;
            // hoist K chunks into registers; reuse across all 16 q-rows
            #pragma unroll
            for (int ch = 0; ch < 6; ch++) {
                unsigned long long kc[8];
                #pragma unroll
                for (int t = 0; t < 8; t++) kc[t] = krow[ch*8 + t];
                #pragma unroll
                for (int q = 0; q < 16; q++) {
                    const unsigned long long* qrow =
                        reinterpret_cast<const unsigned long long*>(&Qs[(half*16+q)*96 + ch*16]);
                    #pragma unroll
                    for (int t = 0; t < 8; t++) ffma2(dotp[q], qrow[t], kc[t]);
                }
            }
            #pragma unroll
            for (int q = 0; q < 16; q++) {
                int qi = half*16 + q;
                float2 du = unpack2(dotp[q]);
                float dot = du.x + du.y;
                float d2 = qq[qi] + kk - 2.f*dot;
                Ssm[j*SST + qi] = sqrtf(fmaxf(d2, 0.f)) * scale;
            }
        }
        __syncthreads();

        // ---- online softmax, thread per q-row ----
        if (tid < nq) {
            float mold = mrow[tid];
            float mt = mold;
            for (int jj = 0; jj < kn; jj++) mt = fmaxf(mt, Ssm[jj*SST + tid]);
            float f = __expf(mold - mt);
            float l = lrow[tid] * f;
            for (int jj = 0; jj < kn; jj++) {
                float p = __expf(Ssm[jj*SST + tid] - mt);
                Ssm[jj*SST + tid] = p;
                l += p;
            }
            for (int jj = kn; jj < AT_KT; jj++) Ssm[jj*SST + tid] = 0.f;
            mrow[tid] = mt; lrow[tid] = l; frow[tid] = f;
        } else if (tid < AT_QT) {
            for (int jj = 0; jj < AT_KT; jj++) Ssm[jj*SST + tid] = 0.f;
            frow[tid] = 1.f;
        }
        __syncthreads();

        // ---- AV: thread per output dim d (tid < 96), q-rows paired ----
        if (tid < 96) {
            const unsigned long long* fp = reinterpret_cast<const unsigned long long*>(frow);
            #pragma unroll
            for (int p = 0; p < 16; p++) accp[p] = fmul2(accp[p], fp[p]);
            for (int jj = 0; jj < kn; jj++) {
                unsigned long long vv = splat2(Vs[jj*KVS + tid]);
                const unsigned long long* srow =
                    reinterpret_cast<const unsigned long long*>(&Ssm[jj*SST]);
                #pragma unroll
                for (int p = 0; p < 16; p++) ffma2(accp[p], srow[p], vv);
            }
        }
        __syncthreads();
    }
    if (tid < 96) {
        #pragma unroll
        for (int p = 0; p < 16; p++) {
            float2 u = unpack2(accp[p]);
            int q0 = 2*p, q1 = 2*p + 1;
            if (q0 < nq) O[base + (size_t)(tq0+q0)*DIM + tid] = u.x / lrow[q0];
            if (q1 < nq) O[base + (size_t)(tq0+q1)*DIM + tid] = u.y / lrow[q1];
        }
    }
}

// ---------------- classifier head ----------------
__global__ void head_kernel(const float* __restrict__ hn,
                            const float* __restrict__ pw,
                            const float* __restrict__ pb,
                            float* __restrict__ out)
{
    int b = blockIdx.x;
    int c = threadIdx.x >> 5;
    int lane = threadIdx.x & 31;
    const float* row = hn + (size_t)b*TOK*DIM;
    float s = 0.f;
    for (int d = lane; d < DIM; d += 32) s = fmaf(row[d], pw[d*NCLS + c], s);
    #pragma unroll
    for (int o = 16; o; o >>= 1) s += __shfl_down_sync(0xffffffffu, s, o);
    if (lane == 0) out[b*NCLS + c] = s + pb[c];
}

// ---------------- cross-entropy loss ----------------
__global__ void loss_kernel(const float* __restrict__ logits,
                            const int* __restrict__ tgt,
                            float* __restrict__ out)
{
    if (threadIdx.x == 0 && blockIdx.x == 0) {
        float acc = 0.f;
        for (int b = 0; b < BATCH; b++) {
            float l0 = logits[2*b], l1 = logits[2*b+1];
            float mx = fmaxf(l0, l1);
            float lse = mx + logf(expf(l0-mx) + expf(l1-mx));
            acc += lse - logits[2*b + tgt[b]];
        }
        out[BATCH*NCLS] = acc * (1.0f/BATCH);
    }
}

// ---------------- launch ----------------
extern "C" void kernel_launch(void* const* d_in, const int* in_sizes, int n_in,
                              void* d_out, int out_size)
{
    const float* x       = (const float*)d_in[0];
    const int*   targets = (const int*)  d_in[1];
    const float* conv_w  = (const float*)d_in[2];
    const float* conv_b  = (const float*)d_in[3];
    const float* cls_tok = (const float*)d_in[4];
    const float* pos_emb = (const float*)d_in[5];
    const float* ln1_s   = (const float*)d_in[6];
    const float* ln1_b   = (const float*)d_in[7];
    const float* ln2_s   = (const float*)d_in[8];
    const float* ln2_b   = (const float*)d_in[9];
    const float* wq      = (const float*)d_in[10];
    const float* wk      = (const float*)d_in[11];
    const float* wv      = (const float*)d_in[12];
    const float* wo      = (const float*)d_in[13];
    const float* bo      = (const float*)d_in[14];
    const float* w1      = (const float*)d_in[15];
    const float* b1      = (const float*)d_in[16];
    const float* w2      = (const float*)d_in[17];
    const float* b2      = (const float*)d_in[18];
    const float* lnf_s   = (const float*)d_in[19];
    const float* lnf_b   = (const float*)d_in[20];
    const float* proj_w  = (const float*)d_in[21];
    const float* proj_b  = (const float*)d_in[22];
    float* out = (float*)d_out;

    float *p_patches, *p_pe, *p_h, *p_hn, *p_q, *p_k, *p_v, *p_att, *p_ff;
    cudaGetSymbolAddress((void**)&p_patches, g_patches);
    cudaGetSymbolAddress((void**)&p_pe,      g_pe);
    cudaGetSymbolAddress((void**)&p_h,       g_h);
    cudaGetSymbolAddress((void**)&p_hn,      g_hn);
    cudaGetSymbolAddress((void**)&p_q,       g_q);
    cudaGetSymbolAddress((void**)&p_k,       g_k);
    cudaGetSymbolAddress((void**)&p_v,       g_v);
    cudaGetSymbolAddress((void**)&p_att,     g_att);
    cudaGetSymbolAddress((void**)&p_ff,      g_ff);

    const int attn_smem = ATTN_SMEM_FLOATS * (int)sizeof(float);  // ~71.7 KB
    cudaFuncSetAttribute(attn_kernel, cudaFuncAttributeMaxDynamicSharedMemorySize, attn_smem);

    // --- patch embedding ---
    {
        long n = (long)BATCH*NPAT*KPATCH;
        im2col_kernel<<<(unsigned)((n + 255) / 256), 256>>>(x, p_patches);
    }
    gemm128<true,false,false,false><<<dim3(DIM/128, (BATCH*NPAT)/128), 256>>>(
        BATCH*NPAT, DIM, KPATCH, p_patches, conv_w, nullptr, nullptr, p_pe);
    {
        long n = (long)BT*DIM;
        assemble_kernel<<<(unsigned)((n + 255) / 256), 256>>>(p_pe, conv_b, cls_tok, pos_emb, p_h);
    }

    const int MT = (BT + 127) / 128;   // 129 M-tiles
    for (int i = 0; i < NBLK; i++) {
        const float* wq_i = wq + (size_t)i*DIM*DIM;
        const float* wk_i = wk + (size_t)i*DIM*DIM;
        const float* wv_i = wv + (size_t)i*DIM*DIM;
        const float* wo_i = wo + (size_t)i*DIM*DIM;
        const float* w1_i = w1 + (size_t)i*DIM*FFD;
        const float* w2_i = w2 + (size_t)i*FFD*DIM;

        ln_kernel<<<BT, 128>>>(p_h, ln1_s + i*DIM, ln1_b + i*DIM, p_hn);

        gemm128_qkv<<<dim3(DIM/128, MT, 3), 256>>>(BT, DIM, p_hn,
            wq_i, wk_i, wv_i, p_q, p_k, p_v);

        attn_kernel<<<dim3((TOK + AT_QT - 1)/AT_QT, NHEAD, BATCH), 128, attn_smem>>>(p_q, p_k, p_v, p_att);

        // h = h + att @ wo + bo
        gemm128<false,true,false,true><<<dim3(DIM/128, MT), 256>>>(BT, DIM, DIM, p_att, wo_i, bo + i*DIM, p_h, p_h);

        ln_kernel<<<BT, 128>>>(p_h, ln2_s + i*DIM, ln2_b + i*DIM, p_hn);

        // ff = relu(hn @ w1 + b1)
        gemm128<false,true,true,false><<<dim3(FFD/128, MT), 256>>>(BT, FFD, DIM, p_hn, w1_i, b1 + i*FFD, nullptr, p_ff);
        // h = h + ff @ w2 + b2
        gemm128<false,true,false,true><<<dim3(DIM/128, MT), 256>>>(BT, DIM, FFD, p_ff, w2_i, b2 + i*DIM, p_h, p_h);
    }

    ln_kernel<<<BT, 128>>>(p_h, lnf_s, lnf_b, p_hn);
    head_kernel<<<BATCH, 64>>>(p_hn, proj_w, proj_b, out);
    loss_kernel<<<1, 32>>>(out, targets, out);
}

// round 11
// speedup vs baseline: 2.3406x; 1.3242x over previous
#include <cuda_runtime.h>
#include <cuda_bf16.h>
#include <math.h>
#include <stdint.h>

// ---------------- problem constants ----------------
#define BATCH 16
#define IMG   512
#define PATCH 16
#define CIN   3
#define DIM   384
#define NHEAD 4
#define HDIM  96
#define NBLK  3
#define NCLS  2
#define NPAT  1024            // (512/16)^2
#define TOK   1025            // NPAT + 1
#define FFD   1536
#define BT    (BATCH*TOK)     // 16400
#define KPATCH (CIN*PATCH*PATCH) // 768
#define QKVD  1152            // fused q|k|v width

// ---------------- packed f32x2 helpers (attention) ----------------
__device__ __forceinline__ unsigned long long splat2(float x) {
    unsigned long long r;
    asm("mov.b64 %0, {%1, %1};" : "=l"(r) : "f"(x));
    return r;
}
__device__ __forceinline__ void ffma2(unsigned long long &d, unsigned long long a, unsigned long long b) {
    asm("fma.rn.f32x2 %0, %1, %2, %0;" : "+l"(d) : "l"(a), "l"(b));
}
__device__ __forceinline__ unsigned long long fmul2(unsigned long long a, unsigned long long b) {
    unsigned long long r;
    asm("mul.rn.f32x2 %0, %1, %2;" : "=l"(r) : "l"(a), "l"(b));
    return r;
}
__device__ __forceinline__ float2 unpack2(unsigned long long v) {
    float2 f;
    asm("mov.b64 {%0, %1}, %2;" : "=f"(f.x), "=f"(f.y) : "l"(v));
    return f;
}

// ---------------- mma.sync m16n8k16 bf16 (baseline sm_80+ — compiles on sm_103) ----
__device__ __forceinline__ void mma16816(float* c, const uint32_t* a, const uint32_t* b) {
    asm volatile(
        "mma.sync.aligned.m16n8k16.row.col.f32.bf16.bf16.f32 "
        "{%0,%1,%2,%3}, {%4,%5,%6,%7}, {%8,%9}, {%0,%1,%2,%3};"
        : "+f"(c[0]), "+f"(c[1]), "+f"(c[2]), "+f"(c[3])
        : "r"(a[0]), "r"(a[1]), "r"(a[2]), "r"(a[3]), "r"(b[0]), "r"(b[1]));
}

// ---------------- scratch (device globals, no allocs allowed) ----------------
__device__ float g_patches[BATCH*NPAT*KPATCH];
__device__ float g_pe     [BATCH*NPAT*DIM];
__device__ float g_h      [BT*DIM];
__device__ float g_hn     [BT*DIM];
__device__ float g_qkv    [BT*QKVD];
__device__ float g_att    [BT*DIM];
__device__ float g_ff     [BT*FFD];
// split-bf16 weights, K-major [N,K]
__device__ __nv_bfloat16 g_cw_h  [DIM*KPATCH],       g_cw_l  [DIM*KPATCH];
__device__ __nv_bfloat16 g_wqkv_h[NBLK*QKVD*DIM],    g_wqkv_l[NBLK*QKVD*DIM];
__device__ __nv_bfloat16 g_wo_h  [NBLK*DIM*DIM],     g_wo_l  [NBLK*DIM*DIM];
__device__ __nv_bfloat16 g_w1_h  [NBLK*FFD*DIM],     g_w1_l  [NBLK*FFD*DIM];
__device__ __nv_bfloat16 g_w2_h  [NBLK*DIM*FFD],     g_w2_l  [NBLK*DIM*FFD];

// ---------------- weight prep: split / transpose+split ----------------
__global__ void split_kernel(const float* __restrict__ src,
                             __nv_bfloat16* __restrict__ h,
                             __nv_bfloat16* __restrict__ l, int n)
{
    int i = blockIdx.x * blockDim.x + threadIdx.x;
    if (i < n) {
        float x = src[i];
        __nv_bfloat16 hh = __float2bfloat16(x);
        h[i] = hh;
        l[i] = __float2bfloat16(x - __bfloat162float(hh));
    }
}
// src [K,N] row-major -> dst [N,K] row-major (split)
__global__ void tsplit_kernel(const float* __restrict__ src,
                              __nv_bfloat16* __restrict__ h,
                              __nv_bfloat16* __restrict__ l, int K, int N)
{
    int i = blockIdx.x * blockDim.x + threadIdx.x;
    if (i < K*N) {
        int nn = i / K, kk = i - nn*K;
        float x = src[(size_t)kk*N + nn];
        __nv_bfloat16 hh = __float2bfloat16(x);
        h[i] = hh;
        l[i] = __float2bfloat16(x - __bfloat162float(hh));
    }
}

// ---------------- im2col ----------------
__global__ void im2col_kernel(const float* __restrict__ x, float* __restrict__ P)
{
    long idx = (long)blockIdx.x * blockDim.x + threadIdx.x;
    if (idx >= (long)BATCH*NPAT*KPATCH) return;
    int col = (int)(idx % KPATCH);
    long pi  = idx / KPATCH;
    int b  = (int)(pi / NPAT);
    int hw = (int)(pi % NPAT);
    int hh = hw >> 5, ww = hw & 31;
    int c = col >> 8;
    int r = col & 255;
    int p = r >> 4, q = r & 15;
    long xi = (((long)b*CIN + c)*IMG + (hh*PATCH + p))*IMG + (ww*PATCH + q);
    P[idx] = x[xi];
}

// ---------------- assemble h = [cls; pe+conv_b] + pos_emb ----------------
__global__ void assemble_kernel(const float* __restrict__ pe,
                                const float* __restrict__ conv_b,
                                const float* __restrict__ cls_tok,
                                const float* __restrict__ pos_emb,
                                float* __restrict__ h)
{
    long idx = (long)blockIdx.x * blockDim.x + threadIdx.x;
    if (idx >= (long)BT*DIM) return;
    int d  = (int)(idx % DIM);
    long bt = idx / DIM;
    int b   = (int)(bt / TOK);
    int tok = (int)(bt % TOK);
    float v = pos_emb[tok*DIM + d];
    if (tok == 0) v += cls_tok[d];
    else          v += pe[((long)b*NPAT + (tok-1))*DIM + d] + conv_b[d];
    h[idx] = v;
}

// ---------------- LayerNorm ----------------
__global__ void ln_kernel(const float* __restrict__ X,
                          const float* __restrict__ gam,
                          const float* __restrict__ bet,
                          float* __restrict__ Y)
{
    int row = blockIdx.x;
    const float* xr = X + (size_t)row*DIM;
    int t = threadIdx.x;
    float x0 = xr[t], x1 = xr[t+128], x2 = xr[t+256];
    float s = x0 + x1 + x2;
    __shared__ float red[4];
    __shared__ float red2[4];
    #pragma unroll
    for (int o = 16; o; o >>= 1) s += __shfl_down_sync(0xffffffffu, s, o);
    int w = t >> 5, l = t & 31;
    if (l == 0) red[w] = s;
    __syncthreads();
    if (t == 0) red[0] = (red[0]+red[1]+red[2]+red[3]) * (1.0f/DIM);
    __syncthreads();
    float mean = red[0];
    float d0 = x0-mean, d1 = x1-mean, d2 = x2-mean;
    float q = d0*d0 + d1*d1 + d2*d2;
    #pragma unroll
    for (int o = 16; o; o >>= 1) q += __shfl_down_sync(0xffffffffu, q, o);
    if (l == 0) red2[w] = q;
    __syncthreads();
    if (t == 0) red2[0] = rsqrtf((red2[0]+red2[1]+red2[2]+red2[3]) * (1.0f/DIM) + 1e-5f);
    __syncthreads();
    float rstd = red2[0];
    float* yr = Y + (size_t)row*DIM;
    yr[t]     = d0*rstd*gam[t]     + bet[t];
    yr[t+128] = d1*rstd*gam[t+128] + bet[t+128];
    yr[t+256] = d2*rstd*gam[t+256] + bet[t+256];
}

// ---------------- split-bf16 tensor-core GEMM (mma.sync m16n8k16) ----------------
// C[M,N] = A[M,K] @ B^T (+bias)(relu)(+res).  A fp32 MxK; B split bf16 [N,K].
// Block tile 128x128, BK=32, 8 warps (2m x 4n), warp tile 64x32.
// N % 128 == 0, K % 32 == 0 required (holds). M guarded.
#define GPAD 40                              // smem row stride (bf16 elems)
#define GBUF (128*GPAD*2)                    // one array (bytes) = 10240
#define GSMEM_BYTES (2*4*GBUF)               // 81920

template<bool BIAS, bool RELU, bool RES>
__global__ __launch_bounds__(256)
void mma_gemm(int M, int N, int K,
              const float* __restrict__ A,
              const __nv_bfloat16* __restrict__ Bh,
              const __nv_bfloat16* __restrict__ Bl,
              const float* __restrict__ bias,
              const float* __restrict__ Res,
              float* __restrict__ C)
{
    extern __shared__ char sm[];
    const int tid = threadIdx.x;
    const int wid = tid >> 5, lane = tid & 31;
    const int wm = wid >> 2, wn = wid & 3;        // warp grid 2 x 4
    const int g = lane >> 2, tg = lane & 3;
    const int bm = blockIdx.y * 128;
    const int bn = blockIdx.x * 128;

    // loader indices
    const int lrow = tid >> 1;                    // 0..127
    const int lkc  = (tid & 1) * 16;              // 0 or 16

    float acc[4][4][4];
    #pragma unroll
    for (int mi = 0; mi < 4; mi++)
        #pragma unroll
        for (int ni = 0; ni < 4; ni++)
            #pragma unroll
            for (int r = 0; r < 4; r++) acc[mi][ni][r] = 0.f;

    // staging registers
    float4 ra[4];
    uint4  rbh[2], rbl[2];

    auto ldg = [&](int k0) {
        const bool aok = (bm + lrow) < M;
        const float* ap = A + (size_t)(bm + lrow)*K + k0 + lkc;
        #pragma unroll
        for (int i = 0; i < 4; i++)
            ra[i] = aok ? *reinterpret_cast<const float4*>(ap + 4*i)
                        : make_float4(0.f,0.f,0.f,0.f);
        size_t bo = (size_t)(bn + lrow)*K + k0 + lkc;
        rbh[0] = *reinterpret_cast<const uint4*>(Bh + bo);
        rbh[1] = *reinterpret_cast<const uint4*>(Bh + bo + 8);
        rbl[0] = *reinterpret_cast<const uint4*>(Bl + bo);
        rbl[1] = *reinterpret_cast<const uint4*>(Bl + bo + 8);
    };
    auto sts = [&](int buf) {
        char* tb = sm + buf * (4*GBUF);
        __nv_bfloat16* Ahs = reinterpret_cast<__nv_bfloat16*>(tb);
        __nv_bfloat16* Als = reinterpret_cast<__nv_bfloat16*>(tb + GBUF);
        #pragma unroll
        for (int i = 0; i < 4; i++) {
            float4 v = ra[i];
            __nv_bfloat162 h01 = __floats2bfloat162_rn(v.x, v.y);
            __nv_bfloat162 h23 = __floats2bfloat162_rn(v.z, v.w);
            float2 r01 = make_float2(v.x - __bfloat162float(h01.x),
                                     v.y - __bfloat162float(h01.y));
            float2 r23 = make_float2(v.z - __bfloat162float(h23.x),
                                     v.w - __bfloat162float(h23.y));
            __nv_bfloat162 l01 = __floats2bfloat162_rn(r01.x, r01.y);
            __nv_bfloat162 l23 = __floats2bfloat162_rn(r23.x, r23.y);
            int eo = lrow*GPAD + lkc + 4*i;
            *reinterpret_cast<__nv_bfloat162*>(Ahs + eo)     = h01;
            *reinterpret_cast<__nv_bfloat162*>(Ahs + eo + 2) = h23;
            *reinterpret_cast<__nv_bfloat162*>(Als + eo)     = l01;
            *reinterpret_cast<__nv_bfloat162*>(Als + eo + 2) = l23;
        }
        uint32_t* Bhs = reinterpret_cast<uint32_t*>(tb + 2*GBUF);
        uint32_t* Bls = reinterpret_cast<uint32_t*>(tb + 3*GBUF);
        int eo2 = (lrow*GPAD + lkc) >> 1;    // uint32 index (2 bf16 each)
        *reinterpret_cast<uint4*>(Bhs + eo2)     = rbh[0];
        *reinterpret_cast<uint4*>(Bhs + eo2 + 4) = rbh[1];
        *reinterpret_cast<uint4*>(Bls + eo2)     = rbl[0];
        *reinterpret_cast<uint4*>(Bls + eo2 + 4) = rbl[1];
    };

    const int nc = K >> 5;                   // BK=32 chunks
    ldg(0); sts(0);
    __syncthreads();

    for (int c = 0; c < nc; c++) {
        const int buf = c & 1;
        const bool more = (c + 1) < nc;
        if (more) ldg((c + 1) << 5);

        char* tb = sm + buf * (4*GBUF);
        const __nv_bfloat16* Ahs = reinterpret_cast<const __nv_bfloat16*>(tb);
        const __nv_bfloat16* Als = reinterpret_cast<const __nv_bfloat16*>(tb + GBUF);
        const __nv_bfloat16* Bhs = reinterpret_cast<const __nv_bfloat16*>(tb + 2*GBUF);
        const __nv_bfloat16* Bls = reinterpret_cast<const __nv_bfloat16*>(tb + 3*GBUF);

        #pragma unroll
        for (int ks = 0; ks < 2; ks++) {
            const int ko = ks*16 + tg*2;
            uint32_t ah[4][4], al[4][4], bh[4][2], bl[4][2];
            #pragma unroll
            for (int mi = 0; mi < 4; mi++) {
                int r0 = (wm*64 + mi*16 + g) * GPAD + ko;
                ah[mi][0] = *reinterpret_cast<const uint32_t*>(Ahs + r0);
                ah[mi][1] = *reinterpret_cast<const uint32_t*>(Ahs + r0 + 8*GPAD);
                ah[mi][2] = *reinterpret_cast<const uint32_t*>(Ahs + r0 + 8);
                ah[mi][3] = *reinterpret_cast<const uint32_t*>(Ahs + r0 + 8*GPAD + 8);
                al[mi][0] = *reinterpret_cast<const uint32_t*>(Als + r0);
                al[mi][1] = *reinterpret_cast<const uint32_t*>(Als + r0 + 8*GPAD);
                al[mi][2] = *reinterpret_cast<const uint32_t*>(Als + r0 + 8);
                al[mi][3] = *reinterpret_cast<const uint32_t*>(Als + r0 + 8*GPAD + 8);
            }
            #pragma unroll
            for (int ni = 0; ni < 4; ni++) {
                int n0 = (wn*32 + ni*8 + g) * GPAD + ko;
                bh[ni][0] = *reinterpret_cast<const uint32_t*>(Bhs + n0);
                bh[ni][1] = *reinterpret_cast<const uint32_t*>(Bhs + n0 + 8);
                bl[ni][0] = *reinterpret_cast<const uint32_t*>(Bls + n0);
                bl[ni][1] = *reinterpret_cast<const uint32_t*>(Bls + n0 + 8);
            }
            #pragma unroll
            for (int mi = 0; mi < 4; mi++)
                #pragma unroll
                for (int ni = 0; ni < 4; ni++) {
                    mma16816(acc[mi][ni], ah[mi], bh[ni]);   // hi*hi
                    mma16816(acc[mi][ni], ah[mi], bl[ni]);   // hi*lo
                    mma16816(acc[mi][ni], al[mi], bh[ni]);   // lo*hi
                }
        }
        if (more) sts(buf ^ 1);
        __syncthreads();
    }

    // ---- epilogue: fragments -> global ----
    #pragma unroll
    for (int mi = 0; mi < 4; mi++) {
        #pragma unroll
        for (int ni = 0; ni < 4; ni++) {
            int row0 = bm + wm*64 + mi*16 + g;
            int col  = bn + wn*32 + ni*8 + tg*2;
            float bx = 0.f, by = 0.f;
            if (BIAS) { bx = bias[col]; by = bias[col+1]; }
            float* cr = acc[mi][ni];
            if (row0 < M) {
                float vx = cr[0] + bx, vy = cr[1] + by;
                if (RELU) { vx = fmaxf(vx, 0.f); vy = fmaxf(vy, 0.f); }
                size_t o = (size_t)row0*N + col;
                if (RES) { float2 r = *reinterpret_cast<const float2*>(Res + o);
                           vx += r.x; vy += r.y; }
                *reinterpret_cast<float2*>(C + o) = make_float2(vx, vy);
            }
            if (row0 + 8 < M) {
                float vx = cr[2] + bx, vy = cr[3] + by;
                if (RELU) { vx = fmaxf(vx, 0.f); vy = fmaxf(vy, 0.f); }
                size_t o = (size_t)(row0+8)*N + col;
                if (RES) { float2 r = *reinterpret_cast<const float2*>(Res + o);
                           vx += r.x; vy += r.y; }
                *reinterpret_cast<float2*>(C + o) = make_float2(vx, vy);
            }
        }
    }
}

// ---------------- fused distance-attention (flash-style, f32x2) ----------------
// reads fused qkv buffer (B, T, 1152); writes O (B, T, 384)
#define AT_QT 32
#define AT_KT 64
#define KVS 98
#define SST 34
#define ATTN_SMEM_FLOATS (2*AT_KT*KVS + AT_QT*96 + AT_KT*SST + 4*AT_QT)
__global__ __launch_bounds__(128)
void attn_kernel(const float* __restrict__ QKV, float* __restrict__ O)
{
    extern __shared__ float smf[];
    float* Ks   = smf;
    float* Vs   = Ks + AT_KT*KVS;
    float* Qs   = Vs + AT_KT*KVS;
    float* Ssm  = Qs + AT_QT*96;            // [64][34] transposed [j][qi]
    float* qq   = Ssm + AT_KT*SST;
    float* mrow = qq + AT_QT;
    float* lrow = mrow + AT_QT;
    float* frow = lrow + AT_QT;

    const int tid = threadIdx.x;
    const int b = blockIdx.z, h = blockIdx.y;
    const int tq0 = blockIdx.x * AT_QT;
    const int nq = min(AT_QT, TOK - tq0);
    const float scale = 0.1020620726f;      // 1/sqrt(96)
    const size_t qbase = ((size_t)b*TOK)*QKVD + h*HDIM;
    const size_t obase = ((size_t)b*TOK)*DIM  + h*HDIM;

    for (int idx = tid; idx < AT_QT*24; idx += 128) {
        int r = idx / 24, c = idx - r*24;
        float4 v = (r < nq) ? *reinterpret_cast<const float4*>(QKV + qbase + (size_t)(tq0+r)*QKVD + 4*c)
                            : make_float4(0.f,0.f,0.f,0.f);
        *reinterpret_cast<float4*>(&Qs[r*96 + 4*c]) = v;
    }
    for (int idx = tid; idx < AT_KT*SST; idx += 128) Ssm[idx] = 0.f;
    __syncthreads();
    if (tid < AT_QT) {
        float s = 0.f;
        #pragma unroll 8
        for (int d = 0; d < 96; d++) { float qv = Qs[tid*96+d]; s += qv*qv; }
        qq[tid] = s; mrow[tid] = -1e30f; lrow[tid] = 0.f; frow[tid] = 1.f;
    }
    unsigned long long accp[16];
    #pragma unroll
    for (int p = 0; p < 16; p++) accp[p] = 0ull;
    __syncthreads();

    const int j    = tid & 63;
    const int half = tid >> 6;

    for (int kt0 = 0; kt0 < TOK; kt0 += AT_KT) {
        int kn = min(AT_KT, TOK - kt0);
        for (int idx = tid; idx < AT_KT*48; idx += 128) {
            int r = idx / 48, c = idx - r*48;
            float2 kv2, vv2;
            if (r < kn) {
                size_t gg = qbase + (size_t)(kt0+r)*QKVD;
                kv2 = *reinterpret_cast<const float2*>(QKV + gg + 384 + 2*c);
                vv2 = *reinterpret_cast<const float2*>(QKV + gg + 768 + 2*c);
            } else { kv2 = make_float2(0.f,0.f); vv2 = kv2; }
            *reinterpret_cast<float2*>(&Ks[r*KVS + 2*c]) = kv2;
            *reinterpret_cast<float2*>(&Vs[r*KVS + 2*c]) = vv2;
        }
        __syncthreads();

        // scores: thread owns key j, 16 q-rows
        {
            const unsigned long long* krow = reinterpret_cast<const unsigned long long*>(&Ks[j*KVS]);
            unsigned long long ka = 0ull, kb = 0ull;
            #pragma unroll
            for (int p = 0; p < 48; p += 2) {
                unsigned long long k0 = krow[p], k1 = krow[p+1];
                ffma2(ka, k0, k0); ffma2(kb, k1, k1);
            }
            float2 ku = unpack2(ka), kv = unpack2(kb);
            float kk = ku.x + ku.y + kv.x + kv.y;

            unsigned long long dotp[16];
            #pragma unroll
            for (int q = 0; q < 16; q++) dotp[q] = 0ull;
            #pragma unroll
            for (int ch = 0; ch < 6; ch++) {
                unsigned long long kc[8];
                #pragma unroll
                for (int t = 0; t < 8; t++) kc[t] = krow[ch*8 + t];
                #pragma unroll
                for (int q = 0; q < 16; q++) {
                    const unsigned long long* qrow =
                        reinterpret_cast<const unsigned long long*>(&Qs[(half*16+q)*96 + ch*16]);
                    #pragma unroll
                    for (int t = 0; t < 8; t++) ffma2(dotp[q], qrow[t], kc[t]);
                }
            }
            #pragma unroll
            for (int q = 0; q < 16; q++) {
                int qi = half*16 + q;
                float2 du = unpack2(dotp[q]);
                float dot = du.x + du.y;
                float d2 = qq[qi] + kk - 2.f*dot;
                Ssm[j*SST + qi] = sqrtf(fmaxf(d2, 0.f)) * scale;
            }
        }
        __syncthreads();

        // online softmax, thread per q-row
        if (tid < nq) {
            float mold = mrow[tid];
            float mt = mold;
            for (int jj = 0; jj < kn; jj++) mt = fmaxf(mt, Ssm[jj*SST + tid]);
            float f = __expf(mold - mt);
            float l = lrow[tid] * f;
            for (int jj = 0; jj < kn; jj++) {
                float p = __expf(Ssm[jj*SST + tid] - mt);
                Ssm[jj*SST + tid] = p;
                l += p;
            }
            for (int jj = kn; jj < AT_KT; jj++) Ssm[jj*SST + tid] = 0.f;
            mrow[tid] = mt; lrow[tid] = l; frow[tid] = f;
        } else if (tid < AT_QT) {
            for (int jj = 0; jj < AT_KT; jj++) Ssm[jj*SST + tid] = 0.f;
            frow[tid] = 1.f;
        }
        __syncthreads();

        // AV: thread per dim d, q-rows paired
        if (tid < 96) {
            const unsigned long long* fp = reinterpret_cast<const unsigned long long*>(frow);
            #pragma unroll
            for (int p = 0; p < 16; p++) accp[p] = fmul2(accp[p], fp[p]);
            for (int jj = 0; jj < kn; jj++) {
                unsigned long long vv = splat2(Vs[jj*KVS + tid]);
                const unsigned long long* srow =
                    reinterpret_cast<const unsigned long long*>(&Ssm[jj*SST]);
                #pragma unroll
                for (int p = 0; p < 16; p++) ffma2(accp[p], srow[p], vv);
            }
        }
        __syncthreads();
    }
    if (tid < 96) {
        #pragma unroll
        for (int p = 0; p < 16; p++) {
            float2 u = unpack2(accp[p]);
            int q0 = 2*p, q1 = 2*p + 1;
            if (q0 < nq) O[obase + (size_t)(tq0+q0)*DIM + tid] = u.x / lrow[q0];
            if (q1 < nq) O[obase + (size_t)(tq0+q1)*DIM + tid] = u.y / lrow[q1];
        }
    }
}

// ---------------- classifier head ----------------
__global__ void head_kernel(const float* __restrict__ hn,
                            const float* __restrict__ pw,
                            const float* __restrict__ pb,
                            float* __restrict__ out)
{
    int b = blockIdx.x;
    int c = threadIdx.x >> 5;
    int lane = threadIdx.x & 31;
    const float* row = hn + (size_t)b*TOK*DIM;
    float s = 0.f;
    for (int d = lane; d < DIM; d += 32) s = fmaf(row[d], pw[d*NCLS + c], s);
    #pragma unroll
    for (int o = 16; o; o >>= 1) s += __shfl_down_sync(0xffffffffu, s, o);
    if (lane == 0) out[b*NCLS + c] = s + pb[c];
}

// ---------------- cross-entropy loss ----------------
__global__ void loss_kernel(const float* __restrict__ logits,
                            const int* __restrict__ tgt,
                            float* __restrict__ out)
{
    if (threadIdx.x == 0 && blockIdx.x == 0) {
        float acc = 0.f;
        for (int b = 0; b < BATCH; b++) {
            float l0 = logits[2*b], l1 = logits[2*b+1];
            float mx = fmaxf(l0, l1);
            float lse = mx + logf(expf(l0-mx) + expf(l1-mx));
            acc += lse - logits[2*b + tgt[b]];
        }
        out[BATCH*NCLS] = acc * (1.0f/BATCH);
    }
}

// ---------------- launch ----------------
extern "C" void kernel_launch(void* const* d_in, const int* in_sizes, int n_in,
                              void* d_out, int out_size)
{
    const float* x       = (const float*)d_in[0];
    const int*   targets = (const int*)  d_in[1];
    const float* conv_w  = (const float*)d_in[2];
    const float* conv_b  = (const float*)d_in[3];
    const float* cls_tok = (const float*)d_in[4];
    const float* pos_emb = (const float*)d_in[5];
    const float* ln1_s   = (const float*)d_in[6];
    const float* ln1_b   = (const float*)d_in[7];
    const float* ln2_s   = (const float*)d_in[8];
    const float* ln2_b   = (const float*)d_in[9];
    const float* wq      = (const float*)d_in[10];
    const float* wk      = (const float*)d_in[11];
    const float* wv      = (const float*)d_in[12];
    const float* wo      = (const float*)d_in[13];
    const float* bo      = (const float*)d_in[14];
    const float* w1      = (const float*)d_in[15];
    const float* b1      = (const float*)d_in[16];
    const float* w2      = (const float*)d_in[17];
    const float* b2      = (const float*)d_in[18];
    const float* lnf_s   = (const float*)d_in[19];
    const float* lnf_b   = (const float*)d_in[20];
    const float* proj_w  = (const float*)d_in[21];
    const float* proj_b  = (const float*)d_in[22];
    float* out = (float*)d_out;

    float *p_patches, *p_pe, *p_h, *p_hn, *p_qkv, *p_att, *p_ff;
    cudaGetSymbolAddress((void**)&p_patches, g_patches);
    cudaGetSymbolAddress((void**)&p_pe,      g_pe);
    cudaGetSymbolAddress((void**)&p_h,       g_h);
    cudaGetSymbolAddress((void**)&p_hn,      g_hn);
    cudaGetSymbolAddress((void**)&p_qkv,     g_qkv);
    cudaGetSymbolAddress((void**)&p_att,     g_att);
    cudaGetSymbolAddress((void**)&p_ff,      g_ff);
    __nv_bfloat16 *cw_h, *cw_l, *wqkv_h, *wqkv_l, *wo_h, *wo_l, *w1_h, *w1_l, *w2_h, *w2_l;
    cudaGetSymbolAddress((void**)&cw_h,   g_cw_h);   cudaGetSymbolAddress((void**)&cw_l,   g_cw_l);
    cudaGetSymbolAddress((void**)&wqkv_h, g_wqkv_h); cudaGetSymbolAddress((void**)&wqkv_l, g_wqkv_l);
    cudaGetSymbolAddress((void**)&wo_h,   g_wo_h);   cudaGetSymbolAddress((void**)&wo_l,   g_wo_l);
    cudaGetSymbolAddress((void**)&w1_h,   g_w1_h);   cudaGetSymbolAddress((void**)&w1_l,   g_w1_l);
    cudaGetSymbolAddress((void**)&w2_h,   g_w2_h);   cudaGetSymbolAddress((void**)&w2_l,   g_w2_l);

    const int attn_smem = ATTN_SMEM_FLOATS * (int)sizeof(float);
    cudaFuncSetAttribute(attn_kernel, cudaFuncAttributeMaxDynamicSharedMemorySize, attn_smem);
    cudaFuncSetAttribute(mma_gemm<false,false,false>, cudaFuncAttributeMaxDynamicSharedMemorySize, GSMEM_BYTES);
    cudaFuncSetAttribute(mma_gemm<true,false,true>,   cudaFuncAttributeMaxDynamicSharedMemorySize, GSMEM_BYTES);
    cudaFuncSetAttribute(mma_gemm<true,true,false>,   cudaFuncAttributeMaxDynamicSharedMemorySize, GSMEM_BYTES);

    // ---- weight prep (split bf16, K-major [N,K]) ----
    split_kernel<<<(DIM*KPATCH + 255)/256, 256>>>(conv_w, cw_h, cw_l, DIM*KPATCH);
    for (int i = 0; i < NBLK; i++) {
        int o = i*QKVD*DIM;
        tsplit_kernel<<<(DIM*DIM + 255)/256, 256>>>(wq + (size_t)i*DIM*DIM,
            wqkv_h + o,              wqkv_l + o,              DIM, DIM);
        tsplit_kernel<<<(DIM*DIM + 255)/256, 256>>>(wk + (size_t)i*DIM*DIM,
            wqkv_h + o + DIM*DIM,    wqkv_l + o + DIM*DIM,    DIM, DIM);
        tsplit_kernel<<<(DIM*DIM + 255)/256, 256>>>(wv + (size_t)i*DIM*DIM,
            wqkv_h + o + 2*DIM*DIM,  wqkv_l + o + 2*DIM*DIM,  DIM, DIM);
        tsplit_kernel<<<(DIM*DIM + 255)/256, 256>>>(wo + (size_t)i*DIM*DIM,
            wo_h + i*DIM*DIM, wo_l + i*DIM*DIM, DIM, DIM);
        tsplit_kernel<<<(DIM*FFD + 255)/256, 256>>>(w1 + (size_t)i*DIM*FFD,
            w1_h + i*FFD*DIM, w1_l + i*FFD*DIM, DIM, FFD);
        tsplit_kernel<<<(FFD*DIM + 255)/256, 256>>>(w2 + (size_t)i*FFD*DIM,
            w2_h + i*DIM*FFD, w2_l + i*DIM*FFD, FFD, DIM);
    }

    // ---- patch embedding ----
    {
        long n = (long)BATCH*NPAT*KPATCH;
        im2col_kernel<<<(unsigned)((n + 255) / 256), 256>>>(x, p_patches);
    }
    mma_gemm<false,false,false><<<dim3(DIM/128, (BATCH*NPAT)/128), 256, GSMEM_BYTES>>>(
        BATCH*NPAT, DIM, KPATCH, p_patches, cw_h, cw_l, nullptr, nullptr, p_pe);
    {
        long n = (long)BT*DIM;
        assemble_kernel<<<(unsigned)((n + 255) / 256), 256>>>(p_pe, conv_b, cls_tok, pos_emb, p_h);
    }

    const int MT = (BT + 127) / 128;   // 129 M-tiles
    for (int i = 0; i < NBLK; i++) {
        ln_kernel<<<BT, 128>>>(p_h, ln1_s + i*DIM, ln1_b + i*DIM, p_hn);

        // fused qkv: (BT,384) @ (384,1152)
        mma_gemm<false,false,false><<<dim3(QKVD/128, MT), 256, GSMEM_BYTES>>>(
            BT, QKVD, DIM, p_hn, wqkv_h + i*QKVD*DIM, wqkv_l + i*QKVD*DIM,
            nullptr, nullptr, p_qkv);

        attn_kernel<<<dim3((TOK + AT_QT - 1)/AT_QT, NHEAD, BATCH), 128, attn_smem>>>(p_qkv, p_att);

        // h = h + att @ wo + bo
        mma_gemm<true,false,true><<<dim3(DIM/128, MT), 256, GSMEM_BYTES>>>(
            BT, DIM, DIM, p_att, wo_h + i*DIM*DIM, wo_l + i*DIM*DIM,
            bo + i*DIM, p_h, p_h);

        ln_kernel<<<BT, 128>>>(p_h, ln2_s + i*DIM, ln2_b + i*DIM, p_hn);

        // ff = relu(hn @ w1 + b1)
        mma_gemm<true,true,false><<<dim3(FFD/128, MT), 256, GSMEM_BYTES>>>(
            BT, FFD, DIM, p_hn, w1_h + i*FFD*DIM, w1_l + i*FFD*DIM,
            b1 + i*FFD, nullptr, p_ff);
        // h = h + ff @ w2 + b2
        mma_gemm<true,false,true><<<dim3(DIM/128, MT), 256, GSMEM_BYTES>>>(
            BT, DIM, FFD, p_ff, w2_h + i*DIM*FFD, w2_l + i*DIM*FFD,
            b2 + i*DIM, p_h, p_h);
    }

    ln_kernel<<<BT, 128>>>(p_h, lnf_s, lnf_b, p_hn);
    head_kernel<<<BATCH, 64>>>(p_hn, proj_w, proj_b, out);
    loss_kernel<<<1, 32>>>(out, targets, out);
}

// round 12
// speedup vs baseline: 2.4625x; 1.0521x over previous
#include <cuda_runtime.h>
#include <cuda_bf16.h>
#include <math.h>
#include <stdint.h>

// ---------------- problem constants ----------------
#define BATCH 16
#define IMG   512
#define PATCH 16
#define CIN   3
#define DIM   384
#define NHEAD 4
#define HDIM  96
#define NBLK  3
#define NCLS  2
#define NPAT  1024            // (512/16)^2
#define TOK   1025            // NPAT + 1
#define FFD   1536
#define BT    (BATCH*TOK)     // 16400
#define KPATCH (CIN*PATCH*PATCH) // 768
#define QKVD  1152            // fused q|k|v width

// ---------------- packed f32x2 helpers (attention) ----------------
__device__ __forceinline__ unsigned long long splat2(float x) {
    unsigned long long r;
    asm("mov.b64 %0, {%1, %1};" : "=l"(r) : "f"(x));
    return r;
}
__device__ __forceinline__ void ffma2(unsigned long long &d, unsigned long long a, unsigned long long b) {
    asm("fma.rn.f32x2 %0, %1, %2, %0;" : "+l"(d) : "l"(a), "l"(b));
}
__device__ __forceinline__ unsigned long long fmul2(unsigned long long a, unsigned long long b) {
    unsigned long long r;
    asm("mul.rn.f32x2 %0, %1, %2;" : "=l"(r) : "l"(a), "l"(b));
    return r;
}
__device__ __forceinline__ float2 unpack2(unsigned long long v) {
    float2 f;
    asm("mov.b64 {%0, %1}, %2;" : "=f"(f.x), "=f"(f.y) : "l"(v));
    return f;
}

// ---------------- mma.sync m16n8k16 bf16 (baseline sm_80+) ----------------
__device__ __forceinline__ void mma16816(float* c, const uint32_t* a, const uint32_t* b) {
    asm volatile(
        "mma.sync.aligned.m16n8k16.row.col.f32.bf16.bf16.f32 "
        "{%0,%1,%2,%3}, {%4,%5,%6,%7}, {%8,%9}, {%0,%1,%2,%3};"
        : "+f"(c[0]), "+f"(c[1]), "+f"(c[2]), "+f"(c[3])
        : "r"(a[0]), "r"(a[1]), "r"(a[2]), "r"(a[3]), "r"(b[0]), "r"(b[1]));
}

// ---------------- cp.async helpers ----------------
__device__ __forceinline__ uint32_t smem_u32(const void* p) {
    uint32_t a;
    asm("{ .reg .u64 t; cvta.to.shared.u64 t, %1; cvt.u32.u64 %0, t; }" : "=r"(a) : "l"(p));
    return a;
}
__device__ __forceinline__ void cpasync16(uint32_t dst, const void* src, int srcbytes) {
    asm volatile("cp.async.ca.shared.global [%0], [%1], 16, %2;"
                 :: "r"(dst), "l"(src), "r"(srcbytes) : "memory");
}
#define CP_COMMIT() asm volatile("cp.async.commit_group;" ::: "memory")

// ---------------- scratch (device globals, no allocs allowed) ----------------
__device__ float g_patches[BATCH*NPAT*KPATCH];
__device__ float g_pe     [BATCH*NPAT*DIM];
__device__ float g_h      [BT*DIM];
__device__ float g_hn     [BT*DIM];
__device__ float g_qkv    [BT*QKVD];
__device__ float g_att    [BT*DIM];
__device__ float g_ff     [BT*FFD];
// split-bf16 A activations (sized for largest: BT x FFD)
__device__ __nv_bfloat16 g_a_h[BT*FFD], g_a_l[BT*FFD];
// split-bf16 weights, K-major [N,K]
__device__ __nv_bfloat16 g_cw_h  [DIM*KPATCH],       g_cw_l  [DIM*KPATCH];
__device__ __nv_bfloat16 g_wqkv_h[NBLK*QKVD*DIM],    g_wqkv_l[NBLK*QKVD*DIM];
__device__ __nv_bfloat16 g_wo_h  [NBLK*DIM*DIM],     g_wo_l  [NBLK*DIM*DIM];
__device__ __nv_bfloat16 g_w1_h  [NBLK*FFD*DIM],     g_w1_l  [NBLK*FFD*DIM];
__device__ __nv_bfloat16 g_w2_h  [NBLK*DIM*FFD],     g_w2_l  [NBLK*DIM*FFD];

// ---------------- A split: fp32 -> bf16 hi/lo (vectorized) ----------------
__global__ void asplit_kernel(const float* __restrict__ src,
                              __nv_bfloat16* __restrict__ h,
                              __nv_bfloat16* __restrict__ l, long n4)
{
    long i = (long)blockIdx.x * blockDim.x + threadIdx.x;
    if (i >= n4) return;
    float4 v = reinterpret_cast<const float4*>(src)[i];
    __nv_bfloat162 h01 = __floats2bfloat162_rn(v.x, v.y);
    __nv_bfloat162 h23 = __floats2bfloat162_rn(v.z, v.w);
    __nv_bfloat162 l01 = __floats2bfloat162_rn(v.x - __bfloat162float(h01.x),
                                               v.y - __bfloat162float(h01.y));
    __nv_bfloat162 l23 = __floats2bfloat162_rn(v.z - __bfloat162float(h23.x),
                                               v.w - __bfloat162float(h23.y));
    reinterpret_cast<__nv_bfloat162*>(h)[2*i]   = h01;
    reinterpret_cast<__nv_bfloat162*>(h)[2*i+1] = h23;
    reinterpret_cast<__nv_bfloat162*>(l)[2*i]   = l01;
    reinterpret_cast<__nv_bfloat162*>(l)[2*i+1] = l23;
}

// ---------------- weight prep (batched over layers via blockIdx.y) ----------------
__global__ void split_kernel(const float* __restrict__ src,
                             __nv_bfloat16* __restrict__ h,
                             __nv_bfloat16* __restrict__ l, int n)
{
    int i = blockIdx.x * blockDim.x + threadIdx.x;
    if (i < n) {
        float x = src[i];
        __nv_bfloat16 hh = __float2bfloat16(x);
        h[i] = hh;
        l[i] = __float2bfloat16(x - __bfloat162float(hh));
    }
}
// src [K,N] row-major -> dst [N,K] row-major (split); layer = blockIdx.y
__global__ void tsplit_kernel(const float* __restrict__ src,
                              __nv_bfloat16* __restrict__ h,
                              __nv_bfloat16* __restrict__ l, int K, int N,
                              long srcStride, long dstStride)
{
    int layer = blockIdx.y;
    src += (size_t)layer * srcStride;
    h   += (size_t)layer * dstStride;
    l   += (size_t)layer * dstStride;
    int i = blockIdx.x * blockDim.x + threadIdx.x;
    if (i < K*N) {
        int nn = i / K, kk = i - nn*K;
        float x = src[(size_t)kk*N + nn];
        __nv_bfloat16 hh = __float2bfloat16(x);
        h[i] = hh;
        l[i] = __float2bfloat16(x - __bfloat162float(hh));
    }
}

// ---------------- im2col ----------------
__global__ void im2col_kernel(const float* __restrict__ x, float* __restrict__ P)
{
    long idx = (long)blockIdx.x * blockDim.x + threadIdx.x;
    if (idx >= (long)BATCH*NPAT*KPATCH) return;
    int col = (int)(idx % KPATCH);
    long pi  = idx / KPATCH;
    int b  = (int)(pi / NPAT);
    int hw = (int)(pi % NPAT);
    int hh = hw >> 5, ww = hw & 31;
    int c = col >> 8;
    int r = col & 255;
    int p = r >> 4, q = r & 15;
    long xi = (((long)b*CIN + c)*IMG + (hh*PATCH + p))*IMG + (ww*PATCH + q);
    P[idx] = x[xi];
}

// ---------------- assemble h = [cls; pe+conv_b] + pos_emb ----------------
__global__ void assemble_kernel(const float* __restrict__ pe,
                                const float* __restrict__ conv_b,
                                const float* __restrict__ cls_tok,
                                const float* __restrict__ pos_emb,
                                float* __restrict__ h)
{
    long idx = (long)blockIdx.x * blockDim.x + threadIdx.x;
    if (idx >= (long)BT*DIM) return;
    int d  = (int)(idx % DIM);
    long bt = idx / DIM;
    int b   = (int)(bt / TOK);
    int tok = (int)(bt % TOK);
    float v = pos_emb[tok*DIM + d];
    if (tok == 0) v += cls_tok[d];
    else          v += pe[((long)b*NPAT + (tok-1))*DIM + d] + conv_b[d];
    h[idx] = v;
}

// ---------------- LayerNorm ----------------
__global__ void ln_kernel(const float* __restrict__ X,
                          const float* __restrict__ gam,
                          const float* __restrict__ bet,
                          float* __restrict__ Y)
{
    int row = blockIdx.x;
    const float* xr = X + (size_t)row*DIM;
    int t = threadIdx.x;
    float x0 = xr[t], x1 = xr[t+128], x2 = xr[t+256];
    float s = x0 + x1 + x2;
    __shared__ float red[4];
    __shared__ float red2[4];
    #pragma unroll
    for (int o = 16; o; o >>= 1) s += __shfl_down_sync(0xffffffffu, s, o);
    int w = t >> 5, l = t & 31;
    if (l == 0) red[w] = s;
    __syncthreads();
    if (t == 0) red[0] = (red[0]+red[1]+red[2]+red[3]) * (1.0f/DIM);
    __syncthreads();
    float mean = red[0];
    float d0 = x0-mean, d1 = x1-mean, d2 = x2-mean;
    float q = d0*d0 + d1*d1 + d2*d2;
    #pragma unroll
    for (int o = 16; o; o >>= 1) q += __shfl_down_sync(0xffffffffu, q, o);
    if (l == 0) red2[w] = q;
    __syncthreads();
    if (t == 0) red2[0] = rsqrtf((red2[0]+red2[1]+red2[2]+red2[3]) * (1.0f/DIM) + 1e-5f);
    __syncthreads();
    float rstd = red2[0];
    float* yr = Y + (size_t)row*DIM;
    yr[t]     = d0*rstd*gam[t]     + bet[t];
    yr[t+128] = d1*rstd*gam[t+128] + bet[t+128];
    yr[t+256] = d2*rstd*gam[t+256] + bet[t+256];
}

// ---------------- split-bf16 tensor-core GEMM (mma.sync + cp.async) ----------------
// C[M,N] = A@B^T (+bias)(relu)(+res).  A split bf16 [M,K]; B split bf16 [N,K].
// Block tile 128x128, BK=32, 8 warps (2m x 4n), warp tile 64x32, cp.async DB.
#define GPAD 40                              // smem row stride (bf16 elems), 80 B
#define GTILE (128*GPAD*2)                   // one tile bytes = 10240
#define GSMEM_BYTES (2*4*GTILE)              // 81920

template<bool BIAS, bool RELU, bool RES>
__global__ __launch_bounds__(256, 2)
void mma_gemm(int M, int N, int K,
              const __nv_bfloat16* __restrict__ Ah,
              const __nv_bfloat16* __restrict__ Al,
              const __nv_bfloat16* __restrict__ Bh,
              const __nv_bfloat16* __restrict__ Bl,
              const float* __restrict__ bias,
              const float* __restrict__ Res,
              float* __restrict__ C)
{
    extern __shared__ char sm[];
    const uint32_t smb = smem_u32(sm);
    const int tid = threadIdx.x;
    const int wid = tid >> 5, lane = tid & 31;
    const int wm = wid >> 2, wn = wid & 3;        // warp grid 2 x 4
    const int g = lane >> 2, tg = lane & 3;
    const int bm = blockIdx.y * 128;
    const int bn = blockIdx.x * 128;

    float acc[4][4][4];
    #pragma unroll
    for (int mi = 0; mi < 4; mi++)
        #pragma unroll
        for (int ni = 0; ni < 4; ni++)
            #pragma unroll
            for (int r = 0; r < 4; r++) acc[mi][ni][r] = 0.f;

    const int lrow = tid >> 2, lseg = tid & 3;    // cp.async mapping

    auto load_buf = [&](int c, int buf) {
        const int k0 = c << 5;
        const uint32_t tb = smb + (uint32_t)buf * (4*GTILE);
        #pragma unroll
        for (int i = 0; i < 2; i++) {
            int r = lrow + i*64;
            uint32_t so = (uint32_t)(r*(GPAD*2) + lseg*16);
            // A (guard M)
            bool ok = (bm + r) < M;
            size_t ao = (size_t)(ok ? bm + r : 0)*K + k0 + lseg*8;
            cpasync16(tb + so,           Ah + ao, ok ? 16 : 0);
            cpasync16(tb + GTILE + so,   Al + ao, ok ? 16 : 0);
            // B (always in range)
            size_t bo2 = (size_t)(bn + r)*K + k0 + lseg*8;
            cpasync16(tb + 2*GTILE + so, Bh + bo2, 16);
            cpasync16(tb + 3*GTILE + so, Bl + bo2, 16);
        }
    };

    const int nc = K >> 5;                   // BK=32 chunks
    load_buf(0, 0);
    CP_COMMIT();

    for (int c = 0; c < nc; c++) {
        const int buf = c & 1;
        const bool more = (c + 1) < nc;
        if (more) { load_buf(c + 1, buf ^ 1); CP_COMMIT(); }
        if (more) asm volatile("cp.async.wait_group 1;" ::: "memory");
        else      asm volatile("cp.async.wait_group 0;" ::: "memory");
        __syncthreads();

        const char* tb = sm + buf * (4*GTILE);
        const __nv_bfloat16* Ahs = reinterpret_cast<const __nv_bfloat16*>(tb);
        const __nv_bfloat16* Als = reinterpret_cast<const __nv_bfloat16*>(tb + GTILE);
        const __nv_bfloat16* Bhs = reinterpret_cast<const __nv_bfloat16*>(tb + 2*GTILE);
        const __nv_bfloat16* Bls = reinterpret_cast<const __nv_bfloat16*>(tb + 3*GTILE);

        #pragma unroll
        for (int ks = 0; ks < 2; ks++) {
            const int ko = ks*16 + tg*2;
            uint32_t bh[4][2], bl[4][2];
            #pragma unroll
            for (int ni = 0; ni < 4; ni++) {
                int n0 = (wn*32 + ni*8 + g) * GPAD + ko;
                bh[ni][0] = *reinterpret_cast<const uint32_t*>(Bhs + n0);
                bh[ni][1] = *reinterpret_cast<const uint32_t*>(Bhs + n0 + 8);
                bl[ni][0] = *reinterpret_cast<const uint32_t*>(Bls + n0);
                bl[ni][1] = *reinterpret_cast<const uint32_t*>(Bls + n0 + 8);
            }
            #pragma unroll
            for (int mi = 0; mi < 4; mi++) {
                int r0 = (wm*64 + mi*16 + g) * GPAD + ko;
                uint32_t ah[4], al[4];
                ah[0] = *reinterpret_cast<const uint32_t*>(Ahs + r0);
                ah[1] = *reinterpret_cast<const uint32_t*>(Ahs + r0 + 8*GPAD);
                ah[2] = *reinterpret_cast<const uint32_t*>(Ahs + r0 + 8);
                ah[3] = *reinterpret_cast<const uint32_t*>(Ahs + r0 + 8*GPAD + 8);
                al[0] = *reinterpret_cast<const uint32_t*>(Als + r0);
                al[1] = *reinterpret_cast<const uint32_t*>(Als + r0 + 8*GPAD);
                al[2] = *reinterpret_cast<const uint32_t*>(Als + r0 + 8);
                al[3] = *reinterpret_cast<const uint32_t*>(Als + r0 + 8*GPAD + 8);
                #pragma unroll
                for (int ni = 0; ni < 4; ni++) {
                    mma16816(acc[mi][ni], ah, bh[ni]);   // hi*hi
                    mma16816(acc[mi][ni], ah, bl[ni]);   // hi*lo
                    mma16816(acc[mi][ni], al, bh[ni]);   // lo*hi
                }
            }
        }
        __syncthreads();
    }

    // ---- epilogue: fragments -> global ----
    #pragma unroll
    for (int mi = 0; mi < 4; mi++) {
        #pragma unroll
        for (int ni = 0; ni < 4; ni++) {
            int row0 = bm + wm*64 + mi*16 + g;
            int col  = bn + wn*32 + ni*8 + tg*2;
            float bx = 0.f, by = 0.f;
            if (BIAS) { bx = bias[col]; by = bias[col+1]; }
            float* cr = acc[mi][ni];
            if (row0 < M) {
                float vx = cr[0] + bx, vy = cr[1] + by;
                if (RELU) { vx = fmaxf(vx, 0.f); vy = fmaxf(vy, 0.f); }
                size_t o = (size_t)row0*N + col;
                if (RES) { float2 r = *reinterpret_cast<const float2*>(Res + o);
                           vx += r.x; vy += r.y; }
                *reinterpret_cast<float2*>(C + o) = make_float2(vx, vy);
            }
            if (row0 + 8 < M) {
                float vx = cr[2] + bx, vy = cr[3] + by;
                if (RELU) { vx = fmaxf(vx, 0.f); vy = fmaxf(vy, 0.f); }
                size_t o = (size_t)(row0+8)*N + col;
                if (RES) { float2 r = *reinterpret_cast<const float2*>(Res + o);
                           vx += r.x; vy += r.y; }
                *reinterpret_cast<float2*>(C + o) = make_float2(vx, vy);
            }
        }
    }
}

// ---------------- fused distance-attention (flash-style, f32x2) ----------------
// reads fused qkv buffer (B, T, 1152); writes O (B, T, 384)
#define AT_QT 32
#define AT_KT 64
#define KVS 98
#define SST 34
#define ATTN_SMEM_FLOATS (2*AT_KT*KVS + AT_QT*96 + AT_KT*SST + 4*AT_QT)
__global__ __launch_bounds__(128)
void attn_kernel(const float* __restrict__ QKV, float* __restrict__ O)
{
    extern __shared__ float smf[];
    float* Ks   = smf;
    float* Vs   = Ks + AT_KT*KVS;
    float* Qs   = Vs + AT_KT*KVS;
    float* Ssm  = Qs + AT_QT*96;            // [64][34] transposed [j][qi]
    float* qq   = Ssm + AT_KT*SST;
    float* mrow = qq + AT_QT;
    float* lrow = mrow + AT_QT;
    float* frow = lrow + AT_QT;

    const int tid = threadIdx.x;
    const int b = blockIdx.z, h = blockIdx.y;
    const int tq0 = blockIdx.x * AT_QT;
    const int nq = min(AT_QT, TOK - tq0);
    const float scale = 0.1020620726f;      // 1/sqrt(96)
    const size_t qbase = ((size_t)b*TOK)*QKVD + h*HDIM;
    const size_t obase = ((size_t)b*TOK)*DIM  + h*HDIM;

    for (int idx = tid; idx < AT_QT*24; idx += 128) {
        int r = idx / 24, c = idx - r*24;
        float4 v = (r < nq) ? *reinterpret_cast<const float4*>(QKV + qbase + (size_t)(tq0+r)*QKVD + 4*c)
                            : make_float4(0.f,0.f,0.f,0.f);
        *reinterpret_cast<float4*>(&Qs[r*96 + 4*c]) = v;
    }
    for (int idx = tid; idx < AT_KT*SST; idx += 128) Ssm[idx] = 0.f;
    __syncthreads();
    if (tid < AT_QT) {
        float s = 0.f;
        #pragma unroll 8
        for (int d = 0; d < 96; d++) { float qv = Qs[tid*96+d]; s += qv*qv; }
        qq[tid] = s; mrow[tid] = -1e30f; lrow[tid] = 0.f; frow[tid] = 1.f;
    }
    unsigned long long accp[16];
    #pragma unroll
    for (int p = 0; p < 16; p++) accp[p] = 0ull;
    __syncthreads();

    const int j    = tid & 63;
    const int half = tid >> 6;

    for (int kt0 = 0; kt0 < TOK; kt0 += AT_KT) {
        int kn = min(AT_KT, TOK - kt0);
        for (int idx = tid; idx < AT_KT*48; idx += 128) {
            int r = idx / 48, c = idx - r*48;
            float2 kv2, vv2;
            if (r < kn) {
                size_t gg = qbase + (size_t)(kt0+r)*QKVD;
                kv2 = *reinterpret_cast<const float2*>(QKV + gg + 384 + 2*c);
                vv2 = *reinterpret_cast<const float2*>(QKV + gg + 768 + 2*c);
            } else { kv2 = make_float2(0.f,0.f); vv2 = kv2; }
            *reinterpret_cast<float2*>(&Ks[r*KVS + 2*c]) = kv2;
            *reinterpret_cast<float2*>(&Vs[r*KVS + 2*c]) = vv2;
        }
        __syncthreads();

        // scores: thread owns key j, 16 q-rows
        {
            const unsigned long long* krow = reinterpret_cast<const unsigned long long*>(&Ks[j*KVS]);
            unsigned long long ka = 0ull, kb = 0ull;
            #pragma unroll
            for (int p = 0; p < 48; p += 2) {
                unsigned long long k0 = krow[p], k1 = krow[p+1];
                ffma2(ka, k0, k0); ffma2(kb, k1, k1);
            }
            float2 ku = unpack2(ka), kv = unpack2(kb);
            float kk = ku.x + ku.y + kv.x + kv.y;

            unsigned long long dotp[16];
            #pragma unroll
            for (int q = 0; q < 16; q++) dotp[q] = 0ull;
            #pragma unroll
            for (int ch = 0; ch < 6; ch++) {
                unsigned long long kc[8];
                #pragma unroll
                for (int t = 0; t < 8; t++) kc[t] = krow[ch*8 + t];
                #pragma unroll
                for (int q = 0; q < 16; q++) {
                    const unsigned long long* qrow =
                        reinterpret_cast<const unsigned long long*>(&Qs[(half*16+q)*96 + ch*16]);
                    #pragma unroll
                    for (int t = 0; t < 8; t++) ffma2(dotp[q], qrow[t], kc[t]);
                }
            }
            #pragma unroll
            for (int q = 0; q < 16; q++) {
                int qi = half*16 + q;
                float2 du = unpack2(dotp[q]);
                float dot = du.x + du.y;
                float d2 = qq[qi] + kk - 2.f*dot;
                Ssm[j*SST + qi] = sqrtf(fmaxf(d2, 0.f)) * scale;
            }
        }
        __syncthreads();

        // online softmax, thread per q-row
        if (tid < nq) {
            float mold = mrow[tid];
            float mt = mold;
            for (int jj = 0; jj < kn; jj++) mt = fmaxf(mt, Ssm[jj*SST + tid]);
            float f = __expf(mold - mt);
            float l = lrow[tid] * f;
            for (int jj = 0; jj < kn; jj++) {
                float p = __expf(Ssm[jj*SST + tid] - mt);
                Ssm[jj*SST + tid] = p;
                l += p;
            }
            for (int jj = kn; jj < AT_KT; jj++) Ssm[jj*SST + tid] = 0.f;
            mrow[tid] = mt; lrow[tid] = l; frow[tid] = f;
        } else if (tid < AT_QT) {
            for (int jj = 0; jj < AT_KT; jj++) Ssm[jj*SST + tid] = 0.f;
            frow[tid] = 1.f;
        }
        __syncthreads();

        // AV: thread per dim d, q-rows paired
        if (tid < 96) {
            const unsigned long long* fp = reinterpret_cast<const unsigned long long*>(frow);
            #pragma unroll
            for (int p = 0; p < 16; p++) accp[p] = fmul2(accp[p], fp[p]);
            for (int jj = 0; jj < kn; jj++) {
                unsigned long long vv = splat2(Vs[jj*KVS + tid]);
                const unsigned long long* srow =
                    reinterpret_cast<const unsigned long long*>(&Ssm[jj*SST]);
                #pragma unroll
                for (int p = 0; p < 16; p++) ffma2(accp[p], srow[p], vv);
            }
        }
        __syncthreads();
    }
    if (tid < 96) {
        #pragma unroll
        for (int p = 0; p < 16; p++) {
            float2 u = unpack2(accp[p]);
            int q0 = 2*p, q1 = 2*p + 1;
            if (q0 < nq) O[obase + (size_t)(tq0+q0)*DIM + tid] = u.x / lrow[q0];
            if (q1 < nq) O[obase + (size_t)(tq0+q1)*DIM + tid] = u.y / lrow[q1];
        }
    }
}

// ---------------- classifier head ----------------
__global__ void head_kernel(const float* __restrict__ hn,
                            const float* __restrict__ pw,
                            const float* __restrict__ pb,
                            float* __restrict__ out)
{
    int b = blockIdx.x;
    int c = threadIdx.x >> 5;
    int lane = threadIdx.x & 31;
    const float* row = hn + (size_t)b*TOK*DIM;
    float s = 0.f;
    for (int d = lane; d < DIM; d += 32) s = fmaf(row[d], pw[d*NCLS + c], s);
    #pragma unroll
    for (int o = 16; o; o >>= 1) s += __shfl_down_sync(0xffffffffu, s, o);
    if (lane == 0) out[b*NCLS + c] = s + pb[c];
}

// ---------------- cross-entropy loss ----------------
__global__ void loss_kernel(const float* __restrict__ logits,
                            const int* __restrict__ tgt,
                            float* __restrict__ out)
{
    if (threadIdx.x == 0 && blockIdx.x == 0) {
        float acc = 0.f;
        for (int b = 0; b < BATCH; b++) {
            float l0 = logits[2*b], l1 = logits[2*b+1];
            float mx = fmaxf(l0, l1);
            float lse = mx + logf(expf(l0-mx) + expf(l1-mx));
            acc += lse - logits[2*b + tgt[b]];
        }
        out[BATCH*NCLS] = acc * (1.0f/BATCH);
    }
}

// ---------------- launch ----------------
extern "C" void kernel_launch(void* const* d_in, const int* in_sizes, int n_in,
                              void* d_out, int out_size)
{
    const float* x       = (const float*)d_in[0];
    const int*   targets = (const int*)  d_in[1];
    const float* conv_w  = (const float*)d_in[2];
    const float* conv_b  = (const float*)d_in[3];
    const float* cls_tok = (const float*)d_in[4];
    const float* pos_emb = (const float*)d_in[5];
    const float* ln1_s   = (const float*)d_in[6];
    const float* ln1_b   = (const float*)d_in[7];
    const float* ln2_s   = (const float*)d_in[8];
    const float* ln2_b   = (const float*)d_in[9];
    const float* wq      = (const float*)d_in[10];
    const float* wk      = (const float*)d_in[11];
    const float* wv      = (const float*)d_in[12];
    const float* wo      = (const float*)d_in[13];
    const float* bo      = (const float*)d_in[14];
    const float* w1      = (const float*)d_in[15];
    const float* b1      = (const float*)d_in[16];
    const float* w2      = (const float*)d_in[17];
    const float* b2      = (const float*)d_in[18];
    const float* lnf_s   = (const float*)d_in[19];
    const float* lnf_b   = (const float*)d_in[20];
    const float* proj_w  = (const float*)d_in[21];
    const float* proj_b  = (const float*)d_in[22];
    float* out = (float*)d_out;

    float *p_patches, *p_pe, *p_h, *p_hn, *p_qkv, *p_att, *p_ff;
    cudaGetSymbolAddress((void**)&p_patches, g_patches);
    cudaGetSymbolAddress((void**)&p_pe,      g_pe);
    cudaGetSymbolAddress((void**)&p_h,       g_h);
    cudaGetSymbolAddress((void**)&p_hn,      g_hn);
    cudaGetSymbolAddress((void**)&p_qkv,     g_qkv);
    cudaGetSymbolAddress((void**)&p_att,     g_att);
    cudaGetSymbolAddress((void**)&p_ff,      g_ff);
    __nv_bfloat16 *a_h, *a_l;
    cudaGetSymbolAddress((void**)&a_h, g_a_h);
    cudaGetSymbolAddress((void**)&a_l, g_a_l);
    __nv_bfloat16 *cw_h, *cw_l, *wqkv_h, *wqkv_l, *wo_h, *wo_l, *w1_h, *w1_l, *w2_h, *w2_l;
    cudaGetSymbolAddress((void**)&cw_h,   g_cw_h);   cudaGetSymbolAddress((void**)&cw_l,   g_cw_l);
    cudaGetSymbolAddress((void**)&wqkv_h, g_wqkv_h); cudaGetSymbolAddress((void**)&wqkv_l, g_wqkv_l);
    cudaGetSymbolAddress((void**)&wo_h,   g_wo_h);   cudaGetSymbolAddress((void**)&wo_l,   g_wo_l);
    cudaGetSymbolAddress((void**)&w1_h,   g_w1_h);   cudaGetSymbolAddress((void**)&w1_l,   g_w1_l);
    cudaGetSymbolAddress((void**)&w2_h,   g_w2_h);   cudaGetSymbolAddress((void**)&w2_l,   g_w2_l);

    const int attn_smem = ATTN_SMEM_FLOATS * (int)sizeof(float);
    cudaFuncSetAttribute(attn_kernel, cudaFuncAttributeMaxDynamicSharedMemorySize, attn_smem);
    cudaFuncSetAttribute(mma_gemm<false,false,false>, cudaFuncAttributeMaxDynamicSharedMemorySize, GSMEM_BYTES);
    cudaFuncSetAttribute(mma_gemm<true,false,true>,   cudaFuncAttributeMaxDynamicSharedMemorySize, GSMEM_BYTES);
    cudaFuncSetAttribute(mma_gemm<true,true,false>,   cudaFuncAttributeMaxDynamicSharedMemorySize, GSMEM_BYTES);

    // ---- weight prep (split bf16, K-major [N,K]); batched over layers ----
    split_kernel<<<(DIM*KPATCH + 255)/256, 256>>>(conv_w, cw_h, cw_l, DIM*KPATCH);
    tsplit_kernel<<<dim3((DIM*DIM + 255)/256, NBLK), 256>>>(wq, wqkv_h, wqkv_l,
        DIM, DIM, (long)DIM*DIM, (long)QKVD*DIM);
    tsplit_kernel<<<dim3((DIM*DIM + 255)/256, NBLK), 256>>>(wk, wqkv_h + DIM*DIM, wqkv_l + DIM*DIM,
        DIM, DIM, (long)DIM*DIM, (long)QKVD*DIM);
    tsplit_kernel<<<dim3((DIM*DIM + 255)/256, NBLK), 256>>>(wv, wqkv_h + 2*DIM*DIM, wqkv_l + 2*DIM*DIM,
        DIM, DIM, (long)DIM*DIM, (long)QKVD*DIM);
    tsplit_kernel<<<dim3((DIM*DIM + 255)/256, NBLK), 256>>>(wo, wo_h, wo_l,
        DIM, DIM, (long)DIM*DIM, (long)DIM*DIM);
    tsplit_kernel<<<dim3((DIM*FFD + 255)/256, NBLK), 256>>>(w1, w1_h, w1_l,
        DIM, FFD, (long)DIM*FFD, (long)FFD*DIM);
    tsplit_kernel<<<dim3((FFD*DIM + 255)/256, NBLK), 256>>>(w2, w2_h, w2_l,
        FFD, DIM, (long)FFD*DIM, (long)DIM*FFD);

    // ---- patch embedding ----
    {
        long n = (long)BATCH*NPAT*KPATCH;
        im2col_kernel<<<(unsigned)((n + 255) / 256), 256>>>(x, p_patches);
        long n4 = n / 4;
        asplit_kernel<<<(unsigned)((n4 + 255) / 256), 256>>>(p_patches, a_h, a_l, n4);
    }
    mma_gemm<false,false,false><<<dim3(DIM/128, (BATCH*NPAT)/128), 256, GSMEM_BYTES>>>(
        BATCH*NPAT, DIM, KPATCH, a_h, a_l, cw_h, cw_l, nullptr, nullptr, p_pe);
    {
        long n = (long)BT*DIM;
        assemble_kernel<<<(unsigned)((n + 255) / 256), 256>>>(p_pe, conv_b, cls_tok, pos_emb, p_h);
    }

    const int MT = (BT + 127) / 128;   // 129 M-tiles
    const long nD4 = (long)BT*DIM/4, nF4 = (long)BT*FFD/4;
    for (int i = 0; i < NBLK; i++) {
        ln_kernel<<<BT, 128>>>(p_h, ln1_s + i*DIM, ln1_b + i*DIM, p_hn);
        asplit_kernel<<<(unsigned)((nD4 + 255)/256), 256>>>(p_hn, a_h, a_l, nD4);

        // fused qkv: (BT,384) @ (384,1152)
        mma_gemm<false,false,false><<<dim3(QKVD/128, MT), 256, GSMEM_BYTES>>>(
            BT, QKVD, DIM, a_h, a_l, wqkv_h + (size_t)i*QKVD*DIM, wqkv_l + (size_t)i*QKVD*DIM,
            nullptr, nullptr, p_qkv);

        attn_kernel<<<dim3((TOK + AT_QT - 1)/AT_QT, NHEAD, BATCH), 128, attn_smem>>>(p_qkv, p_att);

        // h = h + att @ wo + bo
        asplit_kernel<<<(unsigned)((nD4 + 255)/256), 256>>>(p_att, a_h, a_l, nD4);
        mma_gemm<true,false,true><<<dim3(DIM/128, MT), 256, GSMEM_BYTES>>>(
            BT, DIM, DIM, a_h, a_l, wo_h + (size_t)i*DIM*DIM, wo_l + (size_t)i*DIM*DIM,
            bo + i*DIM, p_h, p_h);

        ln_kernel<<<BT, 128>>>(p_h, ln2_s + i*DIM, ln2_b + i*DIM, p_hn);
        asplit_kernel<<<(unsigned)((nD4 + 255)/256), 256>>>(p_hn, a_h, a_l, nD4);

        // ff = relu(hn @ w1 + b1)
        mma_gemm<true,true,false><<<dim3(FFD/128, MT), 256, GSMEM_BYTES>>>(
            BT, FFD, DIM, a_h, a_l, w1_h + (size_t)i*FFD*DIM, w1_l + (size_t)i*FFD*DIM,
            b1 + i*FFD, nullptr, p_ff);
        // h = h + ff @ w2 + b2
        asplit_kernel<<<(unsigned)((nF4 + 255)/256), 256>>>(p_ff, a_h, a_l, nF4);
        mma_gemm<true,false,true><<<dim3(DIM/128, MT), 256, GSMEM_BYTES>>>(
            BT, DIM, FFD, a_h, a_l, w2_h + (size_t)i*DIM*FFD, w2_l + (size_t)i*DIM*FFD,
            b2 + i*DIM, p_h, p_h);
    }

    ln_kernel<<<BT, 128>>>(p_h, lnf_s, lnf_b, p_hn);
    head_kernel<<<BATCH, 64>>>(p_hn, proj_w, proj_b, out);
    loss_kernel<<<1, 32>>>(out, targets, out);
}